// round 3
// baseline (speedup 1.0000x reference)
#include <cuda_runtime.h>
#include <math.h>

// ---------------------------------------------------------------------------
// Problem constants (shapes are fixed by the dataset)
// ---------------------------------------------------------------------------
#define MAXN 125000
#define MAXE 500000

// Scratch (device globals -- no allocation allowed)
__device__ float g_hsum  [(size_t)MAXN * 256];   // [N, H+X] segment sum
__device__ float g_gates [(size_t)MAXN * 512];   // activated gates: f,i,u,o each [N,128]
__device__ float g_ctilde[(size_t)MAXN * 128];   // [N, H]
__device__ float g_B     [256 * 512];            // packed weight matrix B[k][j] = W_gate[j%128][k]
__device__ float g_bias  [512];                  // bW* + b*
__device__ int   g_idx64;                        // 1 if index tensors are int64, 0 if int32

// ---------------------------------------------------------------------------
// Index width detection: if dst_idx is int64, every odd 32-bit word (the high
// half) is 0 (values < 125000). If int32, odd words are random node ids.
// ---------------------------------------------------------------------------
__global__ void k_detect(const unsigned int* __restrict__ words)
{
    int all_hi_zero = 1;
    for (int k = 0; k < 64; ++k) {
        if (words[2 * k + 1] != 0u) { all_hi_zero = 0; break; }
    }
    g_idx64 = all_hi_zero;
}

__device__ __forceinline__ long long load_idx(const void* p, int i, int is64)
{
    return is64 ? ((const long long*)p)[i] : (long long)((const int*)p)[i];
}

// ---------------------------------------------------------------------------
// Zero h_sum and c_tilde (must happen every launch: graph replays)
// ---------------------------------------------------------------------------
__global__ void k_zero(int n4_hsum, int n4_ct)
{
    int i = blockIdx.x * blockDim.x + threadIdx.x;
    float4 z = make_float4(0.f, 0.f, 0.f, 0.f);
    if (i < n4_hsum)                 ((float4*)g_hsum)[i] = z;
    else if (i < n4_hsum + n4_ct)    ((float4*)g_ctilde)[i - n4_hsum] = z;
}

// ---------------------------------------------------------------------------
// Pack the 4 gate weight matrices into B[k][j] (k-major, coalesced for GEMM)
// and fold the two bias vectors per gate.
//   j in [0,128): f | [128,256): i | [256,384): u | [384,512): o
// ---------------------------------------------------------------------------
__global__ void k_pack(const float* __restrict__ Wf, const float* __restrict__ bWf, const float* __restrict__ bf,
                       const float* __restrict__ Wi, const float* __restrict__ bWi, const float* __restrict__ bi,
                       const float* __restrict__ Wu, const float* __restrict__ bWu, const float* __restrict__ bu,
                       const float* __restrict__ Wo, const float* __restrict__ bWo, const float* __restrict__ bo)
{
    int id = blockIdx.x * blockDim.x + threadIdx.x;   // 0 .. 256*512-1
    if (id < 512) {
        int q = id >> 7, j = id & 127;
        const float* bW = (q == 0) ? bWf : (q == 1) ? bWi : (q == 2) ? bWu : bWo;
        const float* bb = (q == 0) ? bf  : (q == 1) ? bi  : (q == 2) ? bu  : bo;
        g_bias[id] = bW[j] + bb[j];
    }
    if (id < 256 * 512) {
        int j = id & 511, k = id >> 9;
        int q = j >> 7, jj = j & 127;
        const float* W = (q == 0) ? Wf : (q == 1) ? Wi : (q == 2) ? Wu : Wo;
        g_B[k * 512 + j] = W[jj * 256 + k];
    }
}

// ---------------------------------------------------------------------------
// Edge message kernel.
// Per edge e with type t, dst d:
//   feat[g]   = sfeat[e,g]*dfeat[e,g] + W_eoh[g,t] + b_eoh[g]        (g<64)
//   edge_w[h] = sum_g feat[g] * W_el[h,g] + b_el[h]                  (h<128)
//   h_sum[d, h]      += h_src[e,h] * edge_w[h]
//   h_sum[d, 128+h]  += embed[e,h]
// One thread per output channel h; W_el row cached in registers per block.
// ---------------------------------------------------------------------------
__global__ __launch_bounds__(128) void k_edge(
    const float* __restrict__ h_src, const float* __restrict__ embed,
    const float* __restrict__ sfeat, const float* __restrict__ dfeat,
    const float* __restrict__ W_eoh, const float* __restrict__ b_eoh,
    const float* __restrict__ W_el,  const float* __restrict__ b_el,
    const void*  __restrict__ etype, const void*  __restrict__ dsti,
    int E)
{
    __shared__ float feat[64];
    const int h = threadIdx.x;

    float w[64];
#pragma unroll
    for (int g = 0; g < 64; ++g) w[g] = W_el[h * 64 + g];
    const float bel  = b_el[h];
    const int   is64 = g_idx64;

    for (int e = blockIdx.x; e < E; e += gridDim.x) {
        __syncthreads();                       // protect feat[] from previous iteration
        if (h < 64) {
            int t = (int)load_idx(etype, e, is64);
            feat[h] = fmaf(sfeat[e * 64 + h], dfeat[e * 64 + h],
                           W_eoh[h * 3 + t] + b_eoh[h]);
        }
        __syncthreads();

        float acc = bel;
#pragma unroll
        for (int g = 0; g < 64; ++g) acc = fmaf(feat[g], w[g], acc);

        long long dst = load_idx(dsti, e, is64);
        float* drow = &g_hsum[dst * 256];
        atomicAdd(drow + h,       h_src[e * 128 + h] * acc);
        atomicAdd(drow + 128 + h, embed[e * 128 + h]);
    }
}

// ---------------------------------------------------------------------------
// Gate GEMM:  g_gates[N,512] = act( h_sum[N,256] @ B[256,512] + bias )
// 128x128x8 tile, 256 threads, 8x8 per thread, packed f32x2 FMA (2 FMA/instr).
// Gate (activation) is uniform per block: q = blockIdx.x  (BN == 128).
// ---------------------------------------------------------------------------
__global__ __launch_bounds__(256) void k_gemm(int N)
{
    __shared__ float As[8][128];
    __shared__ float Bs[8][128];

    const int tid = threadIdx.x;
    const int m0  = blockIdx.y * 128;
    const int j0  = blockIdx.x * 128;
    const int tx  = tid & 15;
    const int ty  = tid >> 4;

    const int arow = tid >> 1;          // 0..127 : A tile row
    const int ak   = (tid & 1) * 4;     // 0 or 4 : K sub-offset
    const int br   = tid >> 5;          // 0..7   : B tile row
    const int bc   = (tid & 31) * 4;    // 0..124 : B tile col

    unsigned long long acc[8][4];
#pragma unroll
    for (int i = 0; i < 8; ++i)
#pragma unroll
        for (int j = 0; j < 4; ++j) acc[i][j] = 0ull;

    const bool a_ok = (m0 + arow) < N;
    const float* Aptr = &g_hsum[(size_t)(m0 + arow) * 256 + ak];

    for (int kb = 0; kb < 256; kb += 8) {
        float4 av = make_float4(0.f, 0.f, 0.f, 0.f);
        if (a_ok) av = *(const float4*)(Aptr + kb);
        float4 bv = *(const float4*)&g_B[(kb + br) * 512 + j0 + bc];

        __syncthreads();
        As[ak + 0][arow] = av.x;
        As[ak + 1][arow] = av.y;
        As[ak + 2][arow] = av.z;
        As[ak + 3][arow] = av.w;
        *(float4*)&Bs[br][bc] = bv;
        __syncthreads();

#pragma unroll
        for (int k = 0; k < 8; ++k) {
            unsigned long long bp[4];
#pragma unroll
            for (int j = 0; j < 4; ++j)
                bp[j] = *(const unsigned long long*)&Bs[k][tx * 8 + 2 * j];
            float a[8];
#pragma unroll
            for (int i = 0; i < 8; ++i) a[i] = As[k][ty * 8 + i];
#pragma unroll
            for (int i = 0; i < 8; ++i) {
                unsigned long long ap;
                asm("mov.b64 %0, {%1, %1};" : "=l"(ap) : "f"(a[i]));
#pragma unroll
                for (int j = 0; j < 4; ++j)
                    asm("fma.rn.f32x2 %0, %1, %2, %0;"
                        : "+l"(acc[i][j]) : "l"(ap), "l"(bp[j]));
            }
        }
    }

    const int q = blockIdx.x;   // gate id: 0=f(sig) 1=i(sig) 2=u(tanh) 3=o(sig)
#pragma unroll
    for (int i = 0; i < 8; ++i) {
        int m = m0 + ty * 8 + i;
        if (m >= N) continue;
#pragma unroll
        for (int jp = 0; jp < 4; ++jp) {
            int j = j0 + tx * 8 + 2 * jp;
            unsigned long long v = acc[i][jp];
            float lo = __uint_as_float((unsigned)(v & 0xffffffffull));
            float hi = __uint_as_float((unsigned)(v >> 32));
            float v0 = lo + g_bias[j];
            float v1 = hi + g_bias[j + 1];
            float r0, r1;
            if (q == 2) { r0 = tanhf(v0);              r1 = tanhf(v1); }
            else        { r0 = 1.f / (1.f + expf(-v0)); r1 = 1.f / (1.f + expf(-v1)); }
            g_gates[(size_t)m * 512 + j]     = r0;
            g_gates[(size_t)m * 512 + j + 1] = r1;
        }
    }
}

// ---------------------------------------------------------------------------
// c_tilde[d,h] += sigmoid_f[d,h] * c_src[e,h]   (f already activated, gate 0)
// ---------------------------------------------------------------------------
__global__ void k_scatter(const float* __restrict__ c_src,
                          const void* __restrict__ dsti, int E)
{
    int id = blockIdx.x * blockDim.x + threadIdx.x;
    int e  = id >> 7;
    if (e >= E) return;
    int h = id & 127;
    long long dst = load_idx(dsti, e, g_idx64);
    float f = g_gates[dst * 512 + h];
    atomicAdd(&g_ctilde[dst * 128 + h], f * c_src[(size_t)e * 128 + h]);
}

// ---------------------------------------------------------------------------
// Finalize: c = i*u + c_tilde ; h = o * tanh(c) ; out = [h | c]  per node
// ---------------------------------------------------------------------------
__global__ void k_final(float* __restrict__ out, int N)
{
    int id = blockIdx.x * blockDim.x + threadIdx.x;
    int n  = id >> 7;
    if (n >= N) return;
    int h = id & 127;
    const float* gr = &g_gates[(size_t)n * 512];
    float ig = gr[128 + h];
    float ug = gr[256 + h];
    float og = gr[384 + h];
    float c  = fmaf(ig, ug, g_ctilde[n * 128 + h]);
    out[(size_t)n * 256 + h]       = og * tanhf(c);
    out[(size_t)n * 256 + 128 + h] = c;
}

// ---------------------------------------------------------------------------
// Launch
// ---------------------------------------------------------------------------
extern "C" void kernel_launch(void* const* d_in, const int* in_sizes, int n_in,
                              void* d_out, int out_size)
{
    const float* h_src = (const float*)d_in[0];
    const float* c_src = (const float*)d_in[1];
    const float* embed = (const float*)d_in[2];
    const float* sfeat = (const float*)d_in[3];
    const float* dfeat = (const float*)d_in[4];
    const float* Wf  = (const float*)d_in[5];
    const float* bWf = (const float*)d_in[6];
    const float* bf  = (const float*)d_in[7];
    const float* Wi  = (const float*)d_in[8];
    const float* bWi = (const float*)d_in[9];
    const float* bi  = (const float*)d_in[10];
    const float* Wu  = (const float*)d_in[11];
    const float* bWu = (const float*)d_in[12];
    const float* bu  = (const float*)d_in[13];
    const float* Wo  = (const float*)d_in[14];
    const float* bWo = (const float*)d_in[15];
    const float* bo  = (const float*)d_in[16];
    const float* W_eoh = (const float*)d_in[17];
    const float* b_eoh = (const float*)d_in[18];
    const float* W_el  = (const float*)d_in[19];
    const float* b_el  = (const float*)d_in[20];
    const void*  etype = d_in[21];
    const void*  dsti  = d_in[22];

    const int E = in_sizes[0] / 128;   // h_src is [E,128]
    const int N = out_size   / 256;    // out   is [N,256]

    // 1) index dtype probe (int32 vs int64)
    k_detect<<<1, 1>>>((const unsigned int*)dsti);

    // 2) zero the scatter targets
    const int n4h = N * 64;            // h_sum float4 count
    const int n4c = N * 32;            // c_tilde float4 count
    const int tot4 = n4h + n4c;
    k_zero<<<(tot4 + 255) / 256, 256>>>(n4h, n4c);

    // 3) pack gate weights + biases
    k_pack<<<512, 256>>>(Wf, bWf, bf, Wi, bWi, bi, Wu, bWu, bu, Wo, bWo, bo);

    // 4) edge messages -> h_sum (atomics)
    k_edge<<<2048, 128>>>(h_src, embed, sfeat, dfeat, W_eoh, b_eoh,
                          W_el, b_el, etype, dsti, E);

    // 5) gate GEMM + activations
    dim3 gg(4, (N + 127) / 128);
    k_gemm<<<gg, 256>>>(N);

    // 6) c_tilde scatter (needs activated f)
    long long scat = (long long)E * 128;
    k_scatter<<<(int)((scat + 255) / 256), 256>>>(c_src, dsti, E);

    // 7) finalize node outputs
    k_final<<<(N * 128 + 255) / 256, 256>>>((float*)d_out, N);
}

// round 4
// speedup vs baseline: 1.2144x; 1.2144x over previous
#include <cuda_runtime.h>
#include <math.h>

// ---------------------------------------------------------------------------
// Problem constants (shapes fixed by the dataset; E/N read at runtime)
// ---------------------------------------------------------------------------
#define MAXN 125000
#define MAXE 500000

// Scratch (device globals -- no allocation allowed)
__device__ float g_hsum  [(size_t)MAXN * 256];   // [N, H+X] segment sum
__device__ float g_gates [(size_t)MAXN * 512];   // activated gates: f,i,u,o each [N,128]
__device__ float g_ctilde[(size_t)MAXN * 128];   // [N, H]
__device__ float g_B     [256 * 512];            // packed gate weights B[k][j] = W_gate[j%128][k]
__device__ float g_bias  [512];                  // bW* + b*
__device__ float g_WelT  [64 * 128];             // W_el^T : [k][h] = W_el[h*64+k]
__device__ int   g_idx64;                        // 1 if index tensors are int64, 0 if int32

// ---------------------------------------------------------------------------
// Index width detection: int64 values < 125000 -> every odd 32-bit word is 0.
// ---------------------------------------------------------------------------
__global__ void k_detect(const unsigned int* __restrict__ words)
{
    int all_hi_zero = 1;
    for (int k = 0; k < 64; ++k) {
        if (words[2 * k + 1] != 0u) { all_hi_zero = 0; break; }
    }
    g_idx64 = all_hi_zero;
}

__device__ __forceinline__ long long load_idx(const void* p, int i, int is64)
{
    return is64 ? ((const long long*)p)[i] : (long long)((const int*)p)[i];
}

// ---------------------------------------------------------------------------
// Zero h_sum and c_tilde (graph replays -> must re-zero every launch)
// ---------------------------------------------------------------------------
__global__ void k_zero(int n4_hsum, int n4_ct)
{
    int i = blockIdx.x * blockDim.x + threadIdx.x;
    float4 z = make_float4(0.f, 0.f, 0.f, 0.f);
    if (i < n4_hsum)                 ((float4*)g_hsum)[i] = z;
    else if (i < n4_hsum + n4_ct)    ((float4*)g_ctilde)[i - n4_hsum] = z;
}

// ---------------------------------------------------------------------------
// Pack gate weights (k-major), biases, and W_el^T
// ---------------------------------------------------------------------------
__global__ void k_pack(const float* __restrict__ Wf, const float* __restrict__ bWf, const float* __restrict__ bf,
                       const float* __restrict__ Wi, const float* __restrict__ bWi, const float* __restrict__ bi,
                       const float* __restrict__ Wu, const float* __restrict__ bWu, const float* __restrict__ bu,
                       const float* __restrict__ Wo, const float* __restrict__ bWo, const float* __restrict__ bo,
                       const float* __restrict__ W_el)
{
    int id = blockIdx.x * blockDim.x + threadIdx.x;   // 0 .. 256*512-1
    if (id < 512) {
        int q = id >> 7, j = id & 127;
        const float* bW = (q == 0) ? bWf : (q == 1) ? bWi : (q == 2) ? bWu : bWo;
        const float* bb = (q == 0) ? bf  : (q == 1) ? bi  : (q == 2) ? bu  : bo;
        g_bias[id] = bW[j] + bb[j];
    }
    if (id < 64 * 128) {              // W_el^T
        int k = id >> 7, j = id & 127;
        g_WelT[id] = W_el[j * 64 + k];
    }
    if (id < 256 * 512) {
        int j = id & 511, k = id >> 9;
        int q = j >> 7, jj = j & 127;
        const float* W = (q == 0) ? Wf : (q == 1) ? Wi : (q == 2) ? Wu : Wo;
        g_B[k * 512 + j] = W[jj * 256 + k];
    }
}

// ---------------------------------------------------------------------------
// Edge-message GEMM + scatter.
// Per block: 128 edges x 128 channels.
//   feat[e,g] = sfeat*dfeat + W_eoh[g, t(e)] + b_eoh[g]      (staged -> As[g][e])
//   edge_w    = feat @ W_el^T + b_el                          (f32x2 GEMM, K=64)
//   epilogue:   h_sum[dst,   c] += h_src[e,c] * edge_w[e,c]
//               h_sum[dst,128+c] += embed[e,c]                (atomics)
// ---------------------------------------------------------------------------
__global__ __launch_bounds__(256, 2) void k_edgemm(
    const float* __restrict__ h_src, const float* __restrict__ embed,
    const float* __restrict__ sfeat, const float* __restrict__ dfeat,
    const float* __restrict__ W_eoh, const float* __restrict__ b_eoh,
    const float* __restrict__ b_el,
    const void*  __restrict__ etype, const void*  __restrict__ dsti,
    int E)
{
    __shared__ float As[64][128];     // feat^T : [g][edge]
    __shared__ float Bs[8][128];      // W_el^T chunk
    __shared__ int   sdst[128];
    __shared__ int   stype[128];
    __shared__ float sWeoh[64 * 3];
    __shared__ float sbeoh[64];
    __shared__ float sbel[128];

    const int tid  = threadIdx.x;
    const int e0   = blockIdx.x * 128;
    const int is64 = g_idx64;

    // ---- stage indices / small params -----------------------------------
    if (tid < 128) {
        int e = e0 + tid;
        if (e < E) {
            stype[tid] = (int)load_idx(etype, e, is64);
            sdst [tid] = (int)load_idx(dsti,  e, is64);
        } else {
            stype[tid] = 0;
            sdst [tid] = -1;
        }
        sbel[tid] = b_el[tid];
    }
    if (tid < 192) sWeoh[tid] = W_eoh[tid];
    if (tid < 64)  sbeoh[tid] = b_eoh[tid];
    __syncthreads();

    // ---- compute feat into As[g][e] -------------------------------------
    {
        const int el = tid & 127;          // local edge
        const int g0 = (tid >> 7) * 4;     // 0 or 4
        const int e  = e0 + el;
        const int t  = stype[el];
        const bool ok = (e < E);
#pragma unroll
        for (int r = 0; r < 8; ++r) {
            int g = g0 + r * 8;            // 0..60 step pattern covers 0..63
            float4 sv = make_float4(0.f, 0.f, 0.f, 0.f);
            float4 dv = make_float4(0.f, 0.f, 0.f, 0.f);
            if (ok) {
                sv = *(const float4*)&sfeat[(size_t)e * 64 + g];
                dv = *(const float4*)&dfeat[(size_t)e * 64 + g];
            }
            As[g + 0][el] = fmaf(sv.x, dv.x, sWeoh[(g + 0) * 3 + t] + sbeoh[g + 0]);
            As[g + 1][el] = fmaf(sv.y, dv.y, sWeoh[(g + 1) * 3 + t] + sbeoh[g + 1]);
            As[g + 2][el] = fmaf(sv.z, dv.z, sWeoh[(g + 2) * 3 + t] + sbeoh[g + 2]);
            As[g + 3][el] = fmaf(sv.w, dv.w, sWeoh[(g + 3) * 3 + t] + sbeoh[g + 3]);
        }
    }

    // ---- GEMM: 8x8 per thread, packed f32x2 FMAs ------------------------
    const int tx = tid & 15;          // channel group
    const int ty = tid >> 4;          // edge group

    unsigned long long acc[8][4];
#pragma unroll
    for (int i = 0; i < 8; ++i)
#pragma unroll
        for (int j = 0; j < 4; ++j) acc[i][j] = 0ull;

    const int bk = tid >> 5;          // 0..7  : Bs row
    const int bj = (tid & 31) * 4;    // 0..124: Bs col

    for (int kb = 0; kb < 64; kb += 8) {
        float4 bv = *(const float4*)&g_WelT[(kb + bk) * 128 + bj];
        __syncthreads();
        *(float4*)&Bs[bk][bj] = bv;
        __syncthreads();

#pragma unroll
        for (int kk = 0; kk < 8; ++kk) {
            unsigned long long bp[4];
#pragma unroll
            for (int j = 0; j < 4; ++j)
                bp[j] = *(const unsigned long long*)&Bs[kk][tx * 8 + 2 * j];
            float a[8];
#pragma unroll
            for (int i = 0; i < 8; ++i) a[i] = As[kb + kk][ty * 8 + i];
#pragma unroll
            for (int i = 0; i < 8; ++i) {
                unsigned long long ap;
                asm("mov.b64 %0, {%1, %1};" : "=l"(ap) : "f"(a[i]));
#pragma unroll
                for (int j = 0; j < 4; ++j)
                    asm("fma.rn.f32x2 %0, %1, %2, %0;"
                        : "+l"(acc[i][j]) : "l"(ap), "l"(bp[j]));
            }
        }
    }

    // ---- epilogue: bias + multiply by h_src + atomic scatter ------------
    float bel[8];
#pragma unroll
    for (int j = 0; j < 8; ++j) bel[j] = sbel[tx * 8 + j];

#pragma unroll
    for (int i = 0; i < 8; ++i) {
        const int el  = ty * 8 + i;
        const int dst = sdst[el];
        if (dst < 0) continue;
        const int e   = e0 + el;
        const float4 h0 = *(const float4*)&h_src[(size_t)e * 128 + tx * 8];
        const float4 h1 = *(const float4*)&h_src[(size_t)e * 128 + tx * 8 + 4];
        const float4 m0 = *(const float4*)&embed[(size_t)e * 128 + tx * 8];
        const float4 m1 = *(const float4*)&embed[(size_t)e * 128 + tx * 8 + 4];
        float* base = &g_hsum[(size_t)dst * 256 + tx * 8];

        float w[8];
#pragma unroll
        for (int jp = 0; jp < 4; ++jp) {
            unsigned long long v = acc[i][jp];
            w[2 * jp]     = __uint_as_float((unsigned)(v & 0xffffffffull)) + bel[2 * jp];
            w[2 * jp + 1] = __uint_as_float((unsigned)(v >> 32))           + bel[2 * jp + 1];
        }
        atomicAdd(base + 0, w[0] * h0.x);
        atomicAdd(base + 1, w[1] * h0.y);
        atomicAdd(base + 2, w[2] * h0.z);
        atomicAdd(base + 3, w[3] * h0.w);
        atomicAdd(base + 4, w[4] * h1.x);
        atomicAdd(base + 5, w[5] * h1.y);
        atomicAdd(base + 6, w[6] * h1.z);
        atomicAdd(base + 7, w[7] * h1.w);
        atomicAdd(base + 128, m0.x);
        atomicAdd(base + 129, m0.y);
        atomicAdd(base + 130, m0.z);
        atomicAdd(base + 131, m0.w);
        atomicAdd(base + 132, m1.x);
        atomicAdd(base + 133, m1.y);
        atomicAdd(base + 134, m1.z);
        atomicAdd(base + 135, m1.w);
    }
}

// ---------------------------------------------------------------------------
// Gate GEMM:  g_gates[N,512] = act( h_sum[N,256] @ B[256,512] + bias )
// 128x128x8 tile, 256 threads, 8x8 per thread, packed f32x2 FMA.
// ---------------------------------------------------------------------------
__global__ __launch_bounds__(256) void k_gemm(int N)
{
    __shared__ float As[8][128];
    __shared__ float Bs[8][128];

    const int tid = threadIdx.x;
    const int m0  = blockIdx.y * 128;
    const int j0  = blockIdx.x * 128;
    const int tx  = tid & 15;
    const int ty  = tid >> 4;

    const int arow = tid >> 1;
    const int ak   = (tid & 1) * 4;
    const int br   = tid >> 5;
    const int bc   = (tid & 31) * 4;

    unsigned long long acc[8][4];
#pragma unroll
    for (int i = 0; i < 8; ++i)
#pragma unroll
        for (int j = 0; j < 4; ++j) acc[i][j] = 0ull;

    const bool a_ok = (m0 + arow) < N;
    const float* Aptr = &g_hsum[(size_t)(m0 + arow) * 256 + ak];

    for (int kb = 0; kb < 256; kb += 8) {
        float4 av = make_float4(0.f, 0.f, 0.f, 0.f);
        if (a_ok) av = *(const float4*)(Aptr + kb);
        float4 bv = *(const float4*)&g_B[(kb + br) * 512 + j0 + bc];

        __syncthreads();
        As[ak + 0][arow] = av.x;
        As[ak + 1][arow] = av.y;
        As[ak + 2][arow] = av.z;
        As[ak + 3][arow] = av.w;
        *(float4*)&Bs[br][bc] = bv;
        __syncthreads();

#pragma unroll
        for (int k = 0; k < 8; ++k) {
            unsigned long long bp[4];
#pragma unroll
            for (int j = 0; j < 4; ++j)
                bp[j] = *(const unsigned long long*)&Bs[k][tx * 8 + 2 * j];
            float a[8];
#pragma unroll
            for (int i = 0; i < 8; ++i) a[i] = As[k][ty * 8 + i];
#pragma unroll
            for (int i = 0; i < 8; ++i) {
                unsigned long long ap;
                asm("mov.b64 %0, {%1, %1};" : "=l"(ap) : "f"(a[i]));
#pragma unroll
                for (int j = 0; j < 4; ++j)
                    asm("fma.rn.f32x2 %0, %1, %2, %0;"
                        : "+l"(acc[i][j]) : "l"(ap), "l"(bp[j]));
            }
        }
    }

    const int q = blockIdx.x;   // gate: 0=f(sig) 1=i(sig) 2=u(tanh) 3=o(sig)
#pragma unroll
    for (int i = 0; i < 8; ++i) {
        int m = m0 + ty * 8 + i;
        if (m >= N) continue;
#pragma unroll
        for (int jp = 0; jp < 4; ++jp) {
            int j = j0 + tx * 8 + 2 * jp;
            unsigned long long v = acc[i][jp];
            float v0 = __uint_as_float((unsigned)(v & 0xffffffffull)) + g_bias[j];
            float v1 = __uint_as_float((unsigned)(v >> 32))           + g_bias[j + 1];
            float r0, r1;
            if (q == 2) { r0 = tanhf(v0);               r1 = tanhf(v1); }
            else        { r0 = 1.f / (1.f + expf(-v0)); r1 = 1.f / (1.f + expf(-v1)); }
            g_gates[(size_t)m * 512 + j]     = r0;
            g_gates[(size_t)m * 512 + j + 1] = r1;
        }
    }
}

// ---------------------------------------------------------------------------
// c_tilde[d, h] += f[d,h] * c_src[e,h]    (float4 per thread)
// ---------------------------------------------------------------------------
__global__ void k_scatter(const float* __restrict__ c_src,
                          const void* __restrict__ dsti, int E)
{
    int id = blockIdx.x * blockDim.x + threadIdx.x;
    int e  = id >> 5;
    if (e >= E) return;
    int h4 = (id & 31) * 4;
    long long dst = load_idx(dsti, e, g_idx64);
    float4 f = *(const float4*)&g_gates[(size_t)dst * 512 + h4];
    float4 c = *(const float4*)&c_src[(size_t)e * 128 + h4];
    float* t = &g_ctilde[(size_t)dst * 128 + h4];
    atomicAdd(t + 0, f.x * c.x);
    atomicAdd(t + 1, f.y * c.y);
    atomicAdd(t + 2, f.z * c.z);
    atomicAdd(t + 3, f.w * c.w);
}

// ---------------------------------------------------------------------------
// Finalize: c = i*u + c_tilde ; h = o*tanh(c) ; out = [h | c]
// ---------------------------------------------------------------------------
__global__ void k_final(float* __restrict__ out, int N)
{
    int id = blockIdx.x * blockDim.x + threadIdx.x;
    int n  = id >> 5;
    if (n >= N) return;
    int h4 = (id & 31) * 4;
    const float* gr = &g_gates[(size_t)n * 512];
    float4 ig = *(const float4*)&gr[128 + h4];
    float4 ug = *(const float4*)&gr[256 + h4];
    float4 og = *(const float4*)&gr[384 + h4];
    float4 ct = *(const float4*)&g_ctilde[(size_t)n * 128 + h4];
    float4 c, h;
    c.x = fmaf(ig.x, ug.x, ct.x);  h.x = og.x * tanhf(c.x);
    c.y = fmaf(ig.y, ug.y, ct.y);  h.y = og.y * tanhf(c.y);
    c.z = fmaf(ig.z, ug.z, ct.z);  h.z = og.z * tanhf(c.z);
    c.w = fmaf(ig.w, ug.w, ct.w);  h.w = og.w * tanhf(c.w);
    *(float4*)&out[(size_t)n * 256 + h4]       = h;
    *(float4*)&out[(size_t)n * 256 + 128 + h4] = c;
}

// ---------------------------------------------------------------------------
// Launch
// ---------------------------------------------------------------------------
extern "C" void kernel_launch(void* const* d_in, const int* in_sizes, int n_in,
                              void* d_out, int out_size)
{
    const float* h_src = (const float*)d_in[0];
    const float* c_src = (const float*)d_in[1];
    const float* embed = (const float*)d_in[2];
    const float* sfeat = (const float*)d_in[3];
    const float* dfeat = (const float*)d_in[4];
    const float* Wf  = (const float*)d_in[5];
    const float* bWf = (const float*)d_in[6];
    const float* bf  = (const float*)d_in[7];
    const float* Wi  = (const float*)d_in[8];
    const float* bWi = (const float*)d_in[9];
    const float* bi  = (const float*)d_in[10];
    const float* Wu  = (const float*)d_in[11];
    const float* bWu = (const float*)d_in[12];
    const float* bu  = (const float*)d_in[13];
    const float* Wo  = (const float*)d_in[14];
    const float* bWo = (const float*)d_in[15];
    const float* bo  = (const float*)d_in[16];
    const float* W_eoh = (const float*)d_in[17];
    const float* b_eoh = (const float*)d_in[18];
    const float* W_el  = (const float*)d_in[19];
    const float* b_el  = (const float*)d_in[20];
    const void*  etype = d_in[21];
    const void*  dsti  = d_in[22];

    const int E = in_sizes[0] / 128;   // h_src is [E,128]
    const int N = out_size   / 256;    // out   is [N,256]

    // 1) index dtype probe (int32 vs int64)
    k_detect<<<1, 1>>>((const unsigned int*)dsti);

    // 2) zero the scatter targets
    const int n4h = N * 64;
    const int n4c = N * 32;
    k_zero<<<(n4h + n4c + 255) / 256, 256>>>(n4h, n4c);

    // 3) pack weights / biases
    k_pack<<<512, 256>>>(Wf, bWf, bf, Wi, bWi, bi, Wu, bWu, bu, Wo, bWo, bo, W_el);

    // 4) edge-message GEMM + scatter into h_sum
    k_edgemm<<<(E + 127) / 128, 256>>>(h_src, embed, sfeat, dfeat,
                                       W_eoh, b_eoh, b_el, etype, dsti, E);

    // 5) gate GEMM + activations
    dim3 gg(4, (N + 127) / 128);
    k_gemm<<<gg, 256>>>(N);

    // 6) c_tilde scatter (needs activated f)
    long long scat = (long long)E * 32;
    k_scatter<<<(int)((scat + 255) / 256), 256>>>(c_src, dsti, E);

    // 7) finalize node outputs
    k_final<<<(N * 32 + 255) / 256, 256>>>((float*)d_out, N);
}

// round 6
// speedup vs baseline: 1.6722x; 1.3770x over previous
#include <cuda_runtime.h>
#include <cuda_bf16.h>
#include <math.h>
#include <stdint.h>

// ---------------------------------------------------------------------------
// Problem constants
// ---------------------------------------------------------------------------
#define MAXN 125000
#define MAXE 500000

// Scratch (device globals -- no allocation allowed)
__device__ float g_hsum  [(size_t)MAXN * 256];   // [N, H+X] segment sum
__device__ float g_gates [(size_t)MAXN * 512];   // activated gates f,i,u,o each [N,128]
__device__ float g_ctilde[(size_t)MAXN * 128];   // [N, H]
__device__ float g_bias  [512];                  // bW* + b*
__device__ float g_WelT  [64 * 128];             // W_el^T
__device__ uint32_t g_Bh2[128 * 512];            // gate W hi: bf16x2 pairs along K  [k2][j]
__device__ uint32_t g_Bl2[128 * 512];            // gate W lo
__device__ int   g_idx64;

// ---------------------------------------------------------------------------
// Helpers
// ---------------------------------------------------------------------------
__device__ __forceinline__ uint32_t packbf2(float x, float y)
{
    __nv_bfloat162 p = __floats2bfloat162_rn(x, y);
    return *(uint32_t*)&p;
}

__device__ __forceinline__ void mma16816(float* d, const uint32_t* a, const uint32_t* b)
{
    asm volatile(
        "mma.sync.aligned.m16n8k16.row.col.f32.bf16.bf16.f32 "
        "{%0,%1,%2,%3}, {%4,%5,%6,%7}, {%8,%9}, {%0,%1,%2,%3};"
        : "+f"(d[0]), "+f"(d[1]), "+f"(d[2]), "+f"(d[3])
        : "r"(a[0]), "r"(a[1]), "r"(a[2]), "r"(a[3]), "r"(b[0]), "r"(b[1]));
}

// ---------------------------------------------------------------------------
// Index dtype detection (int64 values < 125000 -> odd 32-bit words all zero)
// ---------------------------------------------------------------------------
__global__ void k_detect(const unsigned int* __restrict__ words)
{
    int all_hi_zero = 1;
    for (int k = 0; k < 64; ++k)
        if (words[2 * k + 1] != 0u) { all_hi_zero = 0; break; }
    g_idx64 = all_hi_zero;
}
__device__ __forceinline__ long long load_idx(const void* p, int i, int is64)
{
    return is64 ? ((const long long*)p)[i] : (long long)((const int*)p)[i];
}

// ---------------------------------------------------------------------------
// Zero scatter targets (graph replays -> re-zero every launch)
// ---------------------------------------------------------------------------
__global__ void k_zero(int n4_hsum, int n4_ct)
{
    int i = blockIdx.x * blockDim.x + threadIdx.x;
    float4 z = make_float4(0.f, 0.f, 0.f, 0.f);
    if (i < n4_hsum)              ((float4*)g_hsum)[i] = z;
    else if (i < n4_hsum + n4_ct) ((float4*)g_ctilde)[i - n4_hsum] = z;
}

// ---------------------------------------------------------------------------
// Pack biases + W_el^T
// ---------------------------------------------------------------------------
__global__ void k_pack(const float* __restrict__ bWf, const float* __restrict__ bf,
                       const float* __restrict__ bWi, const float* __restrict__ bi,
                       const float* __restrict__ bWu, const float* __restrict__ bu,
                       const float* __restrict__ bWo, const float* __restrict__ bo,
                       const float* __restrict__ W_el)
{
    int id = blockIdx.x * blockDim.x + threadIdx.x;
    if (id < 512) {
        int q = id >> 7, j = id & 127;
        const float* bW = (q == 0) ? bWf : (q == 1) ? bWi : (q == 2) ? bWu : bWo;
        const float* bb = (q == 0) ? bf  : (q == 1) ? bi  : (q == 2) ? bu  : bo;
        g_bias[id] = bW[j] + bb[j];
    }
    if (id < 64 * 128) {
        int k = id >> 7, j = id & 127;
        g_WelT[id] = W_el[j * 64 + k];
    }
}

// ---------------------------------------------------------------------------
// Pack gate weights into bf16 hi/lo k-pair images: g_B?2[k2*512 + j]
//   value = bf16x2( W_q[jj][2*k2], W_q[jj][2*k2+1] ),  q = j>>7, jj = j&127
// ---------------------------------------------------------------------------
__global__ void k_packB(const float* __restrict__ Wf, const float* __restrict__ Wi,
                        const float* __restrict__ Wu, const float* __restrict__ Wo)
{
    int id = blockIdx.x * blockDim.x + threadIdx.x;   // 0 .. 128*512-1
    if (id >= 128 * 512) return;
    int k2 = id >> 9;
    int j  = id & 511;
    int q = j >> 7, jj = j & 127;
    const float* W = (q == 0) ? Wf : (q == 1) ? Wi : (q == 2) ? Wu : Wo;
    float w0 = W[jj * 256 + 2 * k2];
    float w1 = W[jj * 256 + 2 * k2 + 1];
    __nv_bfloat16 h0 = __float2bfloat16(w0);
    __nv_bfloat16 h1 = __float2bfloat16(w1);
    float l0 = w0 - __bfloat162float(h0);
    float l1 = w1 - __bfloat162float(h1);
    g_Bh2[id] = packbf2(__bfloat162float(h0), __bfloat162float(h1));
    g_Bl2[id] = packbf2(l0, l1);
}

// ---------------------------------------------------------------------------
// Edge-message GEMM + scatter (W_el^T fully resident, no in-loop syncs)
// ---------------------------------------------------------------------------
struct EdgeSm {
    float As[64][128];     // feat^T : [g][edge]
    float sW[64 * 128];    // W_el^T
    int   sdst[128];
    int   stype[128];
    float sWeoh[192];
    float sbeoh[64];
    float sbel[128];
};

__global__ __launch_bounds__(256, 2) void k_edgemm(
    const float* __restrict__ h_src, const float* __restrict__ embed,
    const float* __restrict__ sfeat, const float* __restrict__ dfeat,
    const float* __restrict__ W_eoh, const float* __restrict__ b_eoh,
    const float* __restrict__ b_el,
    const void*  __restrict__ etype, const void*  __restrict__ dsti,
    int E)
{
    extern __shared__ char smraw[];
    EdgeSm* sm = (EdgeSm*)smraw;

    const int tid  = threadIdx.x;
    const int e0   = blockIdx.x * 128;
    const int is64 = g_idx64;

    // ---- stage W_el^T + indices + small params --------------------------
#pragma unroll
    for (int r = 0; r < 8; ++r)
        ((float4*)sm->sW)[tid + 256 * r] = ((const float4*)g_WelT)[tid + 256 * r];

    if (tid < 128) {
        int e = e0 + tid;
        if (e < E) {
            sm->stype[tid] = (int)load_idx(etype, e, is64);
            sm->sdst [tid] = (int)load_idx(dsti,  e, is64);
        } else {
            sm->stype[tid] = 0;
            sm->sdst [tid] = -1;
        }
        sm->sbel[tid] = b_el[tid];
    }
    if (tid < 192) sm->sWeoh[tid] = W_eoh[tid];
    if (tid < 64)  sm->sbeoh[tid] = b_eoh[tid];
    __syncthreads();

    // ---- compute feat into As[g][e] -------------------------------------
    {
        const int el = tid & 127;
        const int g0 = (tid >> 7) * 4;
        const int e  = e0 + el;
        const int t  = sm->stype[el];
        const bool ok = (e < E);
#pragma unroll
        for (int r = 0; r < 8; ++r) {
            int g = g0 + r * 8;
            float4 sv = make_float4(0.f, 0.f, 0.f, 0.f);
            float4 dv = make_float4(0.f, 0.f, 0.f, 0.f);
            if (ok) {
                sv = *(const float4*)&sfeat[(size_t)e * 64 + g];
                dv = *(const float4*)&dfeat[(size_t)e * 64 + g];
            }
            sm->As[g + 0][el] = fmaf(sv.x, dv.x, sm->sWeoh[(g + 0) * 3 + t] + sm->sbeoh[g + 0]);
            sm->As[g + 1][el] = fmaf(sv.y, dv.y, sm->sWeoh[(g + 1) * 3 + t] + sm->sbeoh[g + 1]);
            sm->As[g + 2][el] = fmaf(sv.z, dv.z, sm->sWeoh[(g + 2) * 3 + t] + sm->sbeoh[g + 2]);
            sm->As[g + 3][el] = fmaf(sv.w, dv.w, sm->sWeoh[(g + 3) * 3 + t] + sm->sbeoh[g + 3]);
        }
    }
    __syncthreads();

    // ---- GEMM: 8x8 per thread, packed f32x2, no syncs -------------------
    const int tx = tid & 15;
    const int ty = tid >> 4;

    unsigned long long acc[8][4];
#pragma unroll
    for (int i = 0; i < 8; ++i)
#pragma unroll
        for (int j = 0; j < 4; ++j) acc[i][j] = 0ull;

#pragma unroll 4
    for (int k = 0; k < 64; ++k) {
        unsigned long long bp[4];
#pragma unroll
        for (int j = 0; j < 4; ++j)
            bp[j] = *(const unsigned long long*)&sm->sW[k * 128 + tx * 8 + 2 * j];
        float a[8];
#pragma unroll
        for (int i = 0; i < 8; ++i) a[i] = sm->As[k][ty * 8 + i];
#pragma unroll
        for (int i = 0; i < 8; ++i) {
            unsigned long long ap;
            asm("mov.b64 %0, {%1, %1};" : "=l"(ap) : "f"(a[i]));
#pragma unroll
            for (int j = 0; j < 4; ++j)
                asm("fma.rn.f32x2 %0, %1, %2, %0;"
                    : "+l"(acc[i][j]) : "l"(ap), "l"(bp[j]));
        }
    }

    // ---- epilogue: bias + multiply by h_src + atomic scatter ------------
    float bel[8];
#pragma unroll
    for (int j = 0; j < 8; ++j) bel[j] = sm->sbel[tx * 8 + j];

#pragma unroll
    for (int i = 0; i < 8; ++i) {
        const int el  = ty * 8 + i;
        const int dst = sm->sdst[el];
        if (dst < 0) continue;
        const int e   = e0 + el;
        const float4 h0 = *(const float4*)&h_src[(size_t)e * 128 + tx * 8];
        const float4 h1 = *(const float4*)&h_src[(size_t)e * 128 + tx * 8 + 4];
        const float4 m0 = *(const float4*)&embed[(size_t)e * 128 + tx * 8];
        const float4 m1 = *(const float4*)&embed[(size_t)e * 128 + tx * 8 + 4];
        float* base = &g_hsum[(size_t)dst * 256 + tx * 8];

        float w[8];
#pragma unroll
        for (int jp = 0; jp < 4; ++jp) {
            unsigned long long v = acc[i][jp];
            w[2 * jp]     = __uint_as_float((unsigned)(v & 0xffffffffull)) + bel[2 * jp];
            w[2 * jp + 1] = __uint_as_float((unsigned)(v >> 32))           + bel[2 * jp + 1];
        }
        atomicAdd(base + 0, w[0] * h0.x);
        atomicAdd(base + 1, w[1] * h0.y);
        atomicAdd(base + 2, w[2] * h0.z);
        atomicAdd(base + 3, w[3] * h0.w);
        atomicAdd(base + 4, w[4] * h1.x);
        atomicAdd(base + 5, w[5] * h1.y);
        atomicAdd(base + 6, w[6] * h1.z);
        atomicAdd(base + 7, w[7] * h1.w);
        atomicAdd(base + 128, m0.x);
        atomicAdd(base + 129, m0.y);
        atomicAdd(base + 130, m0.z);
        atomicAdd(base + 131, m0.w);
        atomicAdd(base + 132, m1.x);
        atomicAdd(base + 133, m1.y);
        atomicAdd(base + 134, m1.z);
        atomicAdd(base + 135, m1.w);
    }
}

// ---------------------------------------------------------------------------
// Gate GEMM via mma.sync bf16 3-term split:
//   g_gates[N,512] = act( h_sum[N,256] @ B[256,512] + bias )
// grid (4, ceil(N/128)): bx = gate/j-tile (128 cols), by = m-tile (128 rows).
// 8 warps, warp tile 64x32, k-step 16 (16 chunks).
// ---------------------------------------------------------------------------
__global__ __launch_bounds__(256) void k_mgemm(int N)
{
    __shared__ uint32_t Ah2[8][132];   // [k2][m]  bf16x2 hi
    __shared__ uint32_t Al2[8][132];   //          lo
    __shared__ uint32_t Bh2[8][132];   // [k2][j]  hi
    __shared__ uint32_t Bl2[8][132];   //          lo

    const int tid  = threadIdx.x;
    const int lane = tid & 31;
    const int wid  = tid >> 5;
    const int m0   = blockIdx.y * 128;
    const int j0   = blockIdx.x * 128;
    const int wm   = (wid >> 2) * 64;
    const int wj   = (wid & 3) * 32;

    float acc[4][4][4];
#pragma unroll
    for (int i = 0; i < 4; ++i)
#pragma unroll
        for (int j = 0; j < 4; ++j)
#pragma unroll
            for (int r = 0; r < 4; ++r) acc[i][j][r] = 0.f;

    // staging roles
    const int  arow = tid >> 1;
    const int  akq  = tid & 1;             // which 8-K half
    const bool arok = (m0 + arow) < N;
    const int  bbr  = tid >> 5;            // B k2 row 0..7
    const int  bjc  = (tid & 31) * 4;      // B col group

    float4 pa0, pa1;
    uint4  pbh, pbl;

    // prefetch chunk 0
    {
        pa0 = make_float4(0.f, 0.f, 0.f, 0.f);
        pa1 = pa0;
        if (arok) {
            const float* src = &g_hsum[(size_t)(m0 + arow) * 256 + akq * 8];
            pa0 = *(const float4*)(src);
            pa1 = *(const float4*)(src + 4);
        }
        pbh = *(const uint4*)&g_Bh2[(size_t)bbr * 512 + j0 + bjc];
        pbl = *(const uint4*)&g_Bl2[(size_t)bbr * 512 + j0 + bjc];
    }

    const int fr = lane >> 2;     // fragment row/col selector
    const int fk = lane & 3;      // k2 selector

    for (int kc = 0; kc < 16; ++kc) {
        __syncthreads();
        // ---- store staged chunk ----------------------------------------
        {
            const int kb = akq * 4;
            Ah2[kb + 0][arow] = packbf2(__bfloat162float(__float2bfloat16(pa0.x)),
                                        __bfloat162float(__float2bfloat16(pa0.y)));
            Ah2[kb + 1][arow] = packbf2(__bfloat162float(__float2bfloat16(pa0.z)),
                                        __bfloat162float(__float2bfloat16(pa0.w)));
            Ah2[kb + 2][arow] = packbf2(__bfloat162float(__float2bfloat16(pa1.x)),
                                        __bfloat162float(__float2bfloat16(pa1.y)));
            Ah2[kb + 3][arow] = packbf2(__bfloat162float(__float2bfloat16(pa1.z)),
                                        __bfloat162float(__float2bfloat16(pa1.w)));
            Al2[kb + 0][arow] = packbf2(pa0.x - __bfloat162float(__float2bfloat16(pa0.x)),
                                        pa0.y - __bfloat162float(__float2bfloat16(pa0.y)));
            Al2[kb + 1][arow] = packbf2(pa0.z - __bfloat162float(__float2bfloat16(pa0.z)),
                                        pa0.w - __bfloat162float(__float2bfloat16(pa0.w)));
            Al2[kb + 2][arow] = packbf2(pa1.x - __bfloat162float(__float2bfloat16(pa1.x)),
                                        pa1.y - __bfloat162float(__float2bfloat16(pa1.y)));
            Al2[kb + 3][arow] = packbf2(pa1.z - __bfloat162float(__float2bfloat16(pa1.z)),
                                        pa1.w - __bfloat162float(__float2bfloat16(pa1.w)));
            *(uint4*)&Bh2[bbr][bjc] = pbh;
            *(uint4*)&Bl2[bbr][bjc] = pbl;
        }
        __syncthreads();

        // ---- prefetch next chunk ---------------------------------------
        if (kc < 15) {
            pa0 = make_float4(0.f, 0.f, 0.f, 0.f);
            pa1 = pa0;
            if (arok) {
                const float* src = &g_hsum[(size_t)(m0 + arow) * 256 + (kc + 1) * 16 + akq * 8];
                pa0 = *(const float4*)(src);
                pa1 = *(const float4*)(src + 4);
            }
            pbh = *(const uint4*)&g_Bh2[(size_t)((kc + 1) * 8 + bbr) * 512 + j0 + bjc];
            pbl = *(const uint4*)&g_Bl2[(size_t)((kc + 1) * 8 + bbr) * 512 + j0 + bjc];
        }

        // ---- mma on current chunk --------------------------------------
        uint32_t bh[4][2], bl[4][2];
#pragma unroll
        for (int j = 0; j < 4; ++j) {
            const int col = wj + j * 8 + fr;
            bh[j][0] = Bh2[fk][col];
            bh[j][1] = Bh2[fk + 4][col];
            bl[j][0] = Bl2[fk][col];
            bl[j][1] = Bl2[fk + 4][col];
        }
#pragma unroll
        for (int i = 0; i < 4; ++i) {
            const int row = wm + i * 16 + fr;
            uint32_t ah[4] = { Ah2[fk][row], Ah2[fk][row + 8],
                               Ah2[fk + 4][row], Ah2[fk + 4][row + 8] };
            uint32_t al[4] = { Al2[fk][row], Al2[fk][row + 8],
                               Al2[fk + 4][row], Al2[fk + 4][row + 8] };
#pragma unroll
            for (int j = 0; j < 4; ++j) {
                mma16816(acc[i][j], ah, bh[j]);
                mma16816(acc[i][j], ah, bl[j]);
                mma16816(acc[i][j], al, bh[j]);
            }
        }
    }

    // ---- epilogue: bias + activation + store ----------------------------
    const int q = blockIdx.x;   // gate: 0=f 1=i 2=u(tanh) 3=o
#pragma unroll
    for (int j = 0; j < 4; ++j) {
        const int c = j0 + wj + j * 8 + (lane & 3) * 2;
        const float b0 = g_bias[c], b1 = g_bias[c + 1];
#pragma unroll
        for (int i = 0; i < 4; ++i) {
            const int mr = m0 + wm + i * 16 + (lane >> 2);
#pragma unroll
            for (int half = 0; half < 2; ++half) {
                const int m = mr + half * 8;
                if (m >= N) continue;
                float v0 = acc[i][j][half * 2 + 0] + b0;
                float v1 = acc[i][j][half * 2 + 1] + b1;
                float2 o;
                if (q == 2) { o.x = tanhf(v0); o.y = tanhf(v1); }
                else        { o.x = 1.f / (1.f + expf(-v0)); o.y = 1.f / (1.f + expf(-v1)); }
                *(float2*)&g_gates[(size_t)m * 512 + c] = o;
            }
        }
    }
}

// ---------------------------------------------------------------------------
// c_tilde[d, h] += f[d,h] * c_src[e,h]
// ---------------------------------------------------------------------------
__global__ void k_scatter(const float* __restrict__ c_src,
                          const void* __restrict__ dsti, int E)
{
    int id = blockIdx.x * blockDim.x + threadIdx.x;
    int e  = id >> 5;
    if (e >= E) return;
    int h4 = (id & 31) * 4;
    long long dst = load_idx(dsti, e, g_idx64);
    float4 f = *(const float4*)&g_gates[(size_t)dst * 512 + h4];
    float4 c = *(const float4*)&c_src[(size_t)e * 128 + h4];
    float* t = &g_ctilde[(size_t)dst * 128 + h4];
    atomicAdd(t + 0, f.x * c.x);
    atomicAdd(t + 1, f.y * c.y);
    atomicAdd(t + 2, f.z * c.z);
    atomicAdd(t + 3, f.w * c.w);
}

// ---------------------------------------------------------------------------
// Finalize: c = i*u + c_tilde ; h = o*tanh(c) ; out = [h | c]
// ---------------------------------------------------------------------------
__global__ void k_final(float* __restrict__ out, int N)
{
    int id = blockIdx.x * blockDim.x + threadIdx.x;
    int n  = id >> 5;
    if (n >= N) return;
    int h4 = (id & 31) * 4;
    const float* gr = &g_gates[(size_t)n * 512];
    float4 ig = *(const float4*)&gr[128 + h4];
    float4 ug = *(const float4*)&gr[256 + h4];
    float4 og = *(const float4*)&gr[384 + h4];
    float4 ct = *(const float4*)&g_ctilde[(size_t)n * 128 + h4];
    float4 c, h;
    c.x = fmaf(ig.x, ug.x, ct.x);  h.x = og.x * tanhf(c.x);
    c.y = fmaf(ig.y, ug.y, ct.y);  h.y = og.y * tanhf(c.y);
    c.z = fmaf(ig.z, ug.z, ct.z);  h.z = og.z * tanhf(c.z);
    c.w = fmaf(ig.w, ug.w, ct.w);  h.w = og.w * tanhf(c.w);
    *(float4*)&out[(size_t)n * 256 + h4]       = h;
    *(float4*)&out[(size_t)n * 256 + 128 + h4] = c;
}

// ---------------------------------------------------------------------------
// Launch
// ---------------------------------------------------------------------------
extern "C" void kernel_launch(void* const* d_in, const int* in_sizes, int n_in,
                              void* d_out, int out_size)
{
    const float* h_src = (const float*)d_in[0];
    const float* c_src = (const float*)d_in[1];
    const float* embed = (const float*)d_in[2];
    const float* sfeat = (const float*)d_in[3];
    const float* dfeat = (const float*)d_in[4];
    const float* Wf  = (const float*)d_in[5];
    const float* bWf = (const float*)d_in[6];
    const float* bf  = (const float*)d_in[7];
    const float* Wi  = (const float*)d_in[8];
    const float* bWi = (const float*)d_in[9];
    const float* bi  = (const float*)d_in[10];
    const float* Wu  = (const float*)d_in[11];
    const float* bWu = (const float*)d_in[12];
    const float* bu  = (const float*)d_in[13];
    const float* Wo  = (const float*)d_in[14];
    const float* bWo = (const float*)d_in[15];
    const float* bo  = (const float*)d_in[16];
    const float* W_eoh = (const float*)d_in[17];
    const float* b_eoh = (const float*)d_in[18];
    const float* W_el  = (const float*)d_in[19];
    const float* b_el  = (const float*)d_in[20];
    const void*  etype = d_in[21];
    const void*  dsti  = d_in[22];

    const int E = in_sizes[0] / 128;
    const int N = out_size   / 256;

    cudaFuncSetAttribute(k_edgemm, cudaFuncAttributeMaxDynamicSharedMemorySize,
                         (int)sizeof(EdgeSm));

    // 1) index dtype probe
    k_detect<<<1, 1>>>((const unsigned int*)dsti);

    // 2) zero scatter targets
    const int n4h = N * 64, n4c = N * 32;
    k_zero<<<(n4h + n4c + 255) / 256, 256>>>(n4h, n4c);

    // 3) pack biases / W_el^T / bf16 gate-weight pair images
    k_pack<<<32, 256>>>(bWf, bf, bWi, bi, bWu, bu, bWo, bo, W_el);
    k_packB<<<256, 256>>>(Wf, Wi, Wu, Wo);

    // 4) edge-message GEMM + scatter into h_sum
    k_edgemm<<<(E + 127) / 128, 256, sizeof(EdgeSm)>>>(
        h_src, embed, sfeat, dfeat, W_eoh, b_eoh, b_el, etype, dsti, E);

    // 5) gate GEMM (mma.sync bf16 3-term) + activations
    dim3 gg(4, (N + 127) / 128);
    k_mgemm<<<gg, 256>>>(N);

    // 6) c_tilde scatter (needs activated f)
    long long scat = (long long)E * 32;
    k_scatter<<<(int)((scat + 255) / 256), 256>>>(c_src, dsti, E);

    // 7) finalize
    k_final<<<(N * 32 + 255) / 256, 256>>>((float*)d_out, N);
}

// round 7
// speedup vs baseline: 1.7811x; 1.0651x over previous
#include <cuda_runtime.h>
#include <cuda_bf16.h>
#include <math.h>
#include <stdint.h>

// ---------------------------------------------------------------------------
// Problem constants
// ---------------------------------------------------------------------------
#define MAXN 125000
#define MAXE 500000

// Scratch (device globals -- no allocation allowed)
__device__ float g_hsum  [(size_t)MAXN * 256];   // [N, H+X] segment sum
__device__ float g_gates [(size_t)MAXN * 512];   // activated gates f,i,u,o each [N,128]
__device__ float g_ctilde[(size_t)MAXN * 128];   // [N, H]
__device__ float g_bias  [512];                  // bW* + b*
__device__ float g_WelT  [64 * 128];             // W_el^T
__device__ uint32_t g_Bh2[128 * 512];            // gate W hi: bf16x2 pairs along K  [k2][j]
__device__ uint32_t g_Bl2[128 * 512];            // gate W lo
__device__ int   g_idx64;

// ---------------------------------------------------------------------------
// Helpers
// ---------------------------------------------------------------------------
__device__ __forceinline__ uint32_t packbf2(float x, float y)
{
    __nv_bfloat162 p = __floats2bfloat162_rn(x, y);
    return *(uint32_t*)&p;
}

// split (x, y) into bf16x2 hi + bf16x2 lo words
__device__ __forceinline__ void split_pair(float x, float y, uint32_t& hi, uint32_t& lo)
{
    __nv_bfloat16 hx = __float2bfloat16(x);
    __nv_bfloat16 hy = __float2bfloat16(y);
    __nv_bfloat162 hp; hp.x = hx; hp.y = hy;
    hi = *(uint32_t*)&hp;
    lo = packbf2(x - __bfloat162float(hx), y - __bfloat162float(hy));
}

__device__ __forceinline__ void mma16816(float* d, const uint32_t* a, const uint32_t* b)
{
    asm volatile(
        "mma.sync.aligned.m16n8k16.row.col.f32.bf16.bf16.f32 "
        "{%0,%1,%2,%3}, {%4,%5,%6,%7}, {%8,%9}, {%0,%1,%2,%3};"
        : "+f"(d[0]), "+f"(d[1]), "+f"(d[2]), "+f"(d[3])
        : "r"(a[0]), "r"(a[1]), "r"(a[2]), "r"(a[3]), "r"(b[0]), "r"(b[1]));
}

// vector reduction: one instruction adds 4 floats to 16B-aligned gmem
__device__ __forceinline__ void red4(float* addr, float a, float b, float c, float d)
{
    asm volatile("red.global.add.v4.f32 [%0], {%1, %2, %3, %4};"
                 :: "l"(addr), "f"(a), "f"(b), "f"(c), "f"(d) : "memory");
}

// ---------------------------------------------------------------------------
// Index dtype detection (int64 values < 125000 -> odd 32-bit words all zero)
// ---------------------------------------------------------------------------
__global__ void k_detect(const unsigned int* __restrict__ words)
{
    int all_hi_zero = 1;
    for (int k = 0; k < 64; ++k)
        if (words[2 * k + 1] != 0u) { all_hi_zero = 0; break; }
    g_idx64 = all_hi_zero;
}
__device__ __forceinline__ long long load_idx(const void* p, int i, int is64)
{
    return is64 ? ((const long long*)p)[i] : (long long)((const int*)p)[i];
}

// ---------------------------------------------------------------------------
// Zero scatter targets (graph replays -> re-zero every launch)
// ---------------------------------------------------------------------------
__global__ void k_zero(int n4_hsum, int n4_ct)
{
    int i = blockIdx.x * blockDim.x + threadIdx.x;
    float4 z = make_float4(0.f, 0.f, 0.f, 0.f);
    if (i < n4_hsum)              ((float4*)g_hsum)[i] = z;
    else if (i < n4_hsum + n4_ct) ((float4*)g_ctilde)[i - n4_hsum] = z;
}

// ---------------------------------------------------------------------------
// Pack biases + W_el^T
// ---------------------------------------------------------------------------
__global__ void k_pack(const float* __restrict__ bWf, const float* __restrict__ bf,
                       const float* __restrict__ bWi, const float* __restrict__ bi,
                       const float* __restrict__ bWu, const float* __restrict__ bu,
                       const float* __restrict__ bWo, const float* __restrict__ bo,
                       const float* __restrict__ W_el)
{
    int id = blockIdx.x * blockDim.x + threadIdx.x;
    if (id < 512) {
        int q = id >> 7, j = id & 127;
        const float* bW = (q == 0) ? bWf : (q == 1) ? bWi : (q == 2) ? bWu : bWo;
        const float* bb = (q == 0) ? bf  : (q == 1) ? bi  : (q == 2) ? bu  : bo;
        g_bias[id] = bW[j] + bb[j];
    }
    if (id < 64 * 128) {
        int k = id >> 7, j = id & 127;
        g_WelT[id] = W_el[j * 64 + k];
    }
}

// ---------------------------------------------------------------------------
// Pack gate weights into bf16 hi/lo k-pair images: g_B?2[k2*512 + j]
// ---------------------------------------------------------------------------
__global__ void k_packB(const float* __restrict__ Wf, const float* __restrict__ Wi,
                        const float* __restrict__ Wu, const float* __restrict__ Wo)
{
    int id = blockIdx.x * blockDim.x + threadIdx.x;   // 0 .. 128*512-1
    if (id >= 128 * 512) return;
    int k2 = id >> 9;
    int j  = id & 511;
    int q = j >> 7, jj = j & 127;
    const float* W = (q == 0) ? Wf : (q == 1) ? Wi : (q == 2) ? Wu : Wo;
    float w0 = W[jj * 256 + 2 * k2];
    float w1 = W[jj * 256 + 2 * k2 + 1];
    uint32_t hi, lo;
    split_pair(w0, w1, hi, lo);
    g_Bh2[id] = hi;
    g_Bl2[id] = lo;
}

// ---------------------------------------------------------------------------
// Edge-message GEMM + scatter (W_el^T resident in smem, v4 vector reductions)
// ---------------------------------------------------------------------------
struct EdgeSm {
    float As[64][128];     // feat^T : [g][edge]
    float sW[64 * 128];    // W_el^T
    int   sdst[128];
    int   stype[128];
    float sWeoh[192];
    float sbeoh[64];
    float sbel[128];
};

__global__ __launch_bounds__(256, 2) void k_edgemm(
    const float* __restrict__ h_src, const float* __restrict__ embed,
    const float* __restrict__ sfeat, const float* __restrict__ dfeat,
    const float* __restrict__ W_eoh, const float* __restrict__ b_eoh,
    const float* __restrict__ b_el,
    const void*  __restrict__ etype, const void*  __restrict__ dsti,
    int E)
{
    extern __shared__ char smraw[];
    EdgeSm* sm = (EdgeSm*)smraw;

    const int tid  = threadIdx.x;
    const int e0   = blockIdx.x * 128;
    const int is64 = g_idx64;

    // ---- stage W_el^T + indices + small params --------------------------
#pragma unroll
    for (int r = 0; r < 8; ++r)
        ((float4*)sm->sW)[tid + 256 * r] = ((const float4*)g_WelT)[tid + 256 * r];

    if (tid < 128) {
        int e = e0 + tid;
        if (e < E) {
            sm->stype[tid] = (int)load_idx(etype, e, is64);
            sm->sdst [tid] = (int)load_idx(dsti,  e, is64);
        } else {
            sm->stype[tid] = 0;
            sm->sdst [tid] = -1;
        }
        sm->sbel[tid] = b_el[tid];
    }
    if (tid < 192) sm->sWeoh[tid] = W_eoh[tid];
    if (tid < 64)  sm->sbeoh[tid] = b_eoh[tid];
    __syncthreads();

    // ---- compute feat into As[g][e] -------------------------------------
    {
        const int el = tid & 127;
        const int g0 = (tid >> 7) * 4;
        const int e  = e0 + el;
        const int t  = sm->stype[el];
        const bool ok = (e < E);
#pragma unroll
        for (int r = 0; r < 8; ++r) {
            int g = g0 + r * 8;
            float4 sv = make_float4(0.f, 0.f, 0.f, 0.f);
            float4 dv = make_float4(0.f, 0.f, 0.f, 0.f);
            if (ok) {
                sv = *(const float4*)&sfeat[(size_t)e * 64 + g];
                dv = *(const float4*)&dfeat[(size_t)e * 64 + g];
            }
            sm->As[g + 0][el] = fmaf(sv.x, dv.x, sm->sWeoh[(g + 0) * 3 + t] + sm->sbeoh[g + 0]);
            sm->As[g + 1][el] = fmaf(sv.y, dv.y, sm->sWeoh[(g + 1) * 3 + t] + sm->sbeoh[g + 1]);
            sm->As[g + 2][el] = fmaf(sv.z, dv.z, sm->sWeoh[(g + 2) * 3 + t] + sm->sbeoh[g + 2]);
            sm->As[g + 3][el] = fmaf(sv.w, dv.w, sm->sWeoh[(g + 3) * 3 + t] + sm->sbeoh[g + 3]);
        }
    }
    __syncthreads();

    // ---- GEMM: 8x8 per thread, packed f32x2, no syncs -------------------
    const int tx = tid & 15;
    const int ty = tid >> 4;

    unsigned long long acc[8][4];
#pragma unroll
    for (int i = 0; i < 8; ++i)
#pragma unroll
        for (int j = 0; j < 4; ++j) acc[i][j] = 0ull;

#pragma unroll 4
    for (int k = 0; k < 64; ++k) {
        unsigned long long bp[4];
#pragma unroll
        for (int j = 0; j < 4; ++j)
            bp[j] = *(const unsigned long long*)&sm->sW[k * 128 + tx * 8 + 2 * j];
        float a[8];
#pragma unroll
        for (int i = 0; i < 8; ++i) a[i] = sm->As[k][ty * 8 + i];
#pragma unroll
        for (int i = 0; i < 8; ++i) {
            unsigned long long ap;
            asm("mov.b64 %0, {%1, %1};" : "=l"(ap) : "f"(a[i]));
#pragma unroll
            for (int j = 0; j < 4; ++j)
                asm("fma.rn.f32x2 %0, %1, %2, %0;"
                    : "+l"(acc[i][j]) : "l"(ap), "l"(bp[j]));
        }
    }

    // ---- epilogue: bias + multiply by h_src + v4 vector reductions ------
    float bel[8];
#pragma unroll
    for (int j = 0; j < 8; ++j) bel[j] = sm->sbel[tx * 8 + j];

#pragma unroll
    for (int i = 0; i < 8; ++i) {
        const int el  = ty * 8 + i;
        const int dst = sm->sdst[el];
        if (dst < 0) continue;
        const int e   = e0 + el;
        const float4 h0 = *(const float4*)&h_src[(size_t)e * 128 + tx * 8];
        const float4 h1 = *(const float4*)&h_src[(size_t)e * 128 + tx * 8 + 4];
        const float4 m0 = *(const float4*)&embed[(size_t)e * 128 + tx * 8];
        const float4 m1 = *(const float4*)&embed[(size_t)e * 128 + tx * 8 + 4];
        float* base = &g_hsum[(size_t)dst * 256 + tx * 8];

        float w[8];
#pragma unroll
        for (int jp = 0; jp < 4; ++jp) {
            unsigned long long v = acc[i][jp];
            w[2 * jp]     = __uint_as_float((unsigned)(v & 0xffffffffull)) + bel[2 * jp];
            w[2 * jp + 1] = __uint_as_float((unsigned)(v >> 32))           + bel[2 * jp + 1];
        }
        red4(base,       w[0] * h0.x, w[1] * h0.y, w[2] * h0.z, w[3] * h0.w);
        red4(base + 4,   w[4] * h1.x, w[5] * h1.y, w[6] * h1.z, w[7] * h1.w);
        red4(base + 128, m0.x, m0.y, m0.z, m0.w);
        red4(base + 132, m1.x, m1.y, m1.z, m1.w);
    }
}

// ---------------------------------------------------------------------------
// Gate GEMM via mma.sync bf16 3-term split, double-buffered (1 sync / chunk):
//   g_gates[N,512] = act( h_sum[N,256] @ B[256,512] + bias )
// grid (4, ceil(N/128)); 8 warps, warp tile 64x32, k-step 16 (16 chunks).
// ---------------------------------------------------------------------------
__global__ __launch_bounds__(256) void k_mgemm(int N)
{
    __shared__ uint32_t Ah2[2][8][132];
    __shared__ uint32_t Al2[2][8][132];
    __shared__ uint32_t Bh2[2][8][132];
    __shared__ uint32_t Bl2[2][8][132];

    const int tid  = threadIdx.x;
    const int lane = tid & 31;
    const int wid  = tid >> 5;
    const int m0   = blockIdx.y * 128;
    const int j0   = blockIdx.x * 128;
    const int wm   = (wid >> 2) * 64;
    const int wj   = (wid & 3) * 32;

    float acc[4][4][4];
#pragma unroll
    for (int i = 0; i < 4; ++i)
#pragma unroll
        for (int j = 0; j < 4; ++j)
#pragma unroll
            for (int r = 0; r < 4; ++r) acc[i][j][r] = 0.f;

    // staging roles
    const int  arow = tid >> 1;
    const int  akq  = tid & 1;             // which 8-K half
    const bool arok = (m0 + arow) < N;
    const int  bbr  = tid >> 5;            // B k2 row 0..7
    const int  bjc  = (tid & 31) * 4;      // B col group

    float4 pa0, pa1;
    uint4  pbh, pbl;

    auto prefetch = [&](int kc) {
        pa0 = make_float4(0.f, 0.f, 0.f, 0.f);
        pa1 = pa0;
        if (arok) {
            const float* src = &g_hsum[(size_t)(m0 + arow) * 256 + kc * 16 + akq * 8];
            pa0 = *(const float4*)(src);
            pa1 = *(const float4*)(src + 4);
        }
        pbh = *(const uint4*)&g_Bh2[(size_t)(kc * 8 + bbr) * 512 + j0 + bjc];
        pbl = *(const uint4*)&g_Bl2[(size_t)(kc * 8 + bbr) * 512 + j0 + bjc];
    };
    auto store_chunk = [&](int buf) {
        const int kb = akq * 4;
        split_pair(pa0.x, pa0.y, Ah2[buf][kb + 0][arow], Al2[buf][kb + 0][arow]);
        split_pair(pa0.z, pa0.w, Ah2[buf][kb + 1][arow], Al2[buf][kb + 1][arow]);
        split_pair(pa1.x, pa1.y, Ah2[buf][kb + 2][arow], Al2[buf][kb + 2][arow]);
        split_pair(pa1.z, pa1.w, Ah2[buf][kb + 3][arow], Al2[buf][kb + 3][arow]);
        *(uint4*)&Bh2[buf][bbr][bjc] = pbh;
        *(uint4*)&Bl2[buf][bbr][bjc] = pbl;
    };

    prefetch(0);
    store_chunk(0);
    __syncthreads();

    const int fr = lane >> 2;     // fragment row/col selector
    const int fk = lane & 3;      // k2 selector

    for (int kc = 0; kc < 16; ++kc) {
        const int cur = kc & 1;
        if (kc < 15) prefetch(kc + 1);

        // ---- mma on current chunk --------------------------------------
        uint32_t bh[4][2], bl[4][2];
#pragma unroll
        for (int j = 0; j < 4; ++j) {
            const int col = wj + j * 8 + fr;
            bh[j][0] = Bh2[cur][fk][col];
            bh[j][1] = Bh2[cur][fk + 4][col];
            bl[j][0] = Bl2[cur][fk][col];
            bl[j][1] = Bl2[cur][fk + 4][col];
        }
#pragma unroll
        for (int i = 0; i < 4; ++i) {
            const int row = wm + i * 16 + fr;
            uint32_t ah[4] = { Ah2[cur][fk][row], Ah2[cur][fk][row + 8],
                               Ah2[cur][fk + 4][row], Ah2[cur][fk + 4][row + 8] };
            uint32_t al[4] = { Al2[cur][fk][row], Al2[cur][fk][row + 8],
                               Al2[cur][fk + 4][row], Al2[cur][fk + 4][row + 8] };
#pragma unroll
            for (int j = 0; j < 4; ++j) {
                mma16816(acc[i][j], ah, bh[j]);
                mma16816(acc[i][j], ah, bl[j]);
                mma16816(acc[i][j], al, bh[j]);
            }
        }

        if (kc < 15) store_chunk(cur ^ 1);
        __syncthreads();
    }

    // ---- epilogue: bias + activation + store ----------------------------
    const int q = blockIdx.x;   // gate: 0=f 1=i 2=u(tanh) 3=o
#pragma unroll
    for (int j = 0; j < 4; ++j) {
        const int c = j0 + wj + j * 8 + (lane & 3) * 2;
        const float b0 = g_bias[c], b1 = g_bias[c + 1];
#pragma unroll
        for (int i = 0; i < 4; ++i) {
            const int mr = m0 + wm + i * 16 + (lane >> 2);
#pragma unroll
            for (int half = 0; half < 2; ++half) {
                const int m = mr + half * 8;
                if (m >= N) continue;
                float v0 = acc[i][j][half * 2 + 0] + b0;
                float v1 = acc[i][j][half * 2 + 1] + b1;
                float2 o;
                if (q == 2) { o.x = tanhf(v0); o.y = tanhf(v1); }
                else        { o.x = 1.f / (1.f + expf(-v0)); o.y = 1.f / (1.f + expf(-v1)); }
                *(float2*)&g_gates[(size_t)m * 512 + c] = o;
            }
        }
    }
}

// ---------------------------------------------------------------------------
// c_tilde[d, h] += f[d,h] * c_src[e,h]   (one v4 reduction per thread)
// ---------------------------------------------------------------------------
__global__ void k_scatter(const float* __restrict__ c_src,
                          const void* __restrict__ dsti, int E)
{
    int id = blockIdx.x * blockDim.x + threadIdx.x;
    int e  = id >> 5;
    if (e >= E) return;
    int h4 = (id & 31) * 4;
    long long dst = load_idx(dsti, e, g_idx64);
    float4 f = *(const float4*)&g_gates[(size_t)dst * 512 + h4];
    float4 c = *(const float4*)&c_src[(size_t)e * 128 + h4];
    red4(&g_ctilde[(size_t)dst * 128 + h4],
         f.x * c.x, f.y * c.y, f.z * c.z, f.w * c.w);
}

// ---------------------------------------------------------------------------
// Finalize: c = i*u + c_tilde ; h = o*tanh(c) ; out = [h | c]
// ---------------------------------------------------------------------------
__global__ void k_final(float* __restrict__ out, int N)
{
    int id = blockIdx.x * blockDim.x + threadIdx.x;
    int n  = id >> 5;
    if (n >= N) return;
    int h4 = (id & 31) * 4;
    const float* gr = &g_gates[(size_t)n * 512];
    float4 ig = *(const float4*)&gr[128 + h4];
    float4 ug = *(const float4*)&gr[256 + h4];
    float4 og = *(const float4*)&gr[384 + h4];
    float4 ct = *(const float4*)&g_ctilde[(size_t)n * 128 + h4];
    float4 c, h;
    c.x = fmaf(ig.x, ug.x, ct.x);  h.x = og.x * tanhf(c.x);
    c.y = fmaf(ig.y, ug.y, ct.y);  h.y = og.y * tanhf(c.y);
    c.z = fmaf(ig.z, ug.z, ct.z);  h.z = og.z * tanhf(c.z);
    c.w = fmaf(ig.w, ug.w, ct.w);  h.w = og.w * tanhf(c.w);
    *(float4*)&out[(size_t)n * 256 + h4]       = h;
    *(float4*)&out[(size_t)n * 256 + 128 + h4] = c;
}

// ---------------------------------------------------------------------------
// Launch
// ---------------------------------------------------------------------------
extern "C" void kernel_launch(void* const* d_in, const int* in_sizes, int n_in,
                              void* d_out, int out_size)
{
    const float* h_src = (const float*)d_in[0];
    const float* c_src = (const float*)d_in[1];
    const float* embed = (const float*)d_in[2];
    const float* sfeat = (const float*)d_in[3];
    const float* dfeat = (const float*)d_in[4];
    const float* Wf  = (const float*)d_in[5];
    const float* bWf = (const float*)d_in[6];
    const float* bf  = (const float*)d_in[7];
    const float* Wi  = (const float*)d_in[8];
    const float* bWi = (const float*)d_in[9];
    const float* bi  = (const float*)d_in[10];
    const float* Wu  = (const float*)d_in[11];
    const float* bWu = (const float*)d_in[12];
    const float* bu  = (const float*)d_in[13];
    const float* Wo  = (const float*)d_in[14];
    const float* bWo = (const float*)d_in[15];
    const float* bo  = (const float*)d_in[16];
    const float* W_eoh = (const float*)d_in[17];
    const float* b_eoh = (const float*)d_in[18];
    const float* W_el  = (const float*)d_in[19];
    const float* b_el  = (const float*)d_in[20];
    const void*  etype = d_in[21];
    const void*  dsti  = d_in[22];

    const int E = in_sizes[0] / 128;
    const int N = out_size   / 256;

    cudaFuncSetAttribute(k_edgemm, cudaFuncAttributeMaxDynamicSharedMemorySize,
                         (int)sizeof(EdgeSm));

    // 1) index dtype probe
    k_detect<<<1, 1>>>((const unsigned int*)dsti);

    // 2) zero scatter targets
    const int n4h = N * 64, n4c = N * 32;
    k_zero<<<(n4h + n4c + 255) / 256, 256>>>(n4h, n4c);

    // 3) pack biases / W_el^T / bf16 gate-weight pair images
    k_pack<<<32, 256>>>(bWf, bf, bWi, bi, bWu, bu, bWo, bo, W_el);
    k_packB<<<256, 256>>>(Wf, Wi, Wu, Wo);

    // 4) edge-message GEMM + scatter into h_sum
    k_edgemm<<<(E + 127) / 128, 256, sizeof(EdgeSm)>>>(
        h_src, embed, sfeat, dfeat, W_eoh, b_eoh, b_el, etype, dsti, E);

    // 5) gate GEMM (mma.sync bf16 3-term, double-buffered) + activations
    dim3 gg(4, (N + 127) / 128);
    k_mgemm<<<gg, 256>>>(N);

    // 6) c_tilde scatter (needs activated f)
    long long scat = (long long)E * 32;
    k_scatter<<<(int)((scat + 255) / 256), 256>>>(c_src, dsti, E);

    // 7) finalize
    k_final<<<(N * 32 + 255) / 256, 256>>>((float*)d_out, N);
}

// round 8
// speedup vs baseline: 2.5517x; 1.4327x over previous
#include <cuda_runtime.h>
#include <cuda_bf16.h>
#include <math.h>
#include <stdint.h>

// ---------------------------------------------------------------------------
// Problem constants
// ---------------------------------------------------------------------------
#define MAXN 125000
#define MAXE 500000

// Scratch (device globals -- no allocation allowed)
__device__ float g_hsum  [(size_t)MAXN * 256];   // [N, H+X] segment sum
__device__ float g_gates [(size_t)MAXN * 512];   // activated gates f,i,u,o each [N,128]
__device__ float g_ctilde[(size_t)MAXN * 128];   // [N, H]
__device__ float g_bias  [512];                  // bW* + b*
__device__ uint32_t g_Bh2[128 * 512];            // gate W hi: bf16x2 pairs along K  [k2][j]
__device__ uint32_t g_Bl2[128 * 512];            // gate W lo
__device__ uint32_t g_Welh2[32 * 128];           // W_el hi: bf16x2 pairs along g  [g2][c]
__device__ uint32_t g_Well2[32 * 128];           // W_el lo
__device__ int   g_idx64;

// ---------------------------------------------------------------------------
// Helpers
// ---------------------------------------------------------------------------
__device__ __forceinline__ uint32_t packbf2(float x, float y)
{
    __nv_bfloat162 p = __floats2bfloat162_rn(x, y);
    return *(uint32_t*)&p;
}

// split (x, y) into bf16x2 hi + bf16x2 lo words
__device__ __forceinline__ void split_pair(float x, float y, uint32_t& hi, uint32_t& lo)
{
    __nv_bfloat16 hx = __float2bfloat16(x);
    __nv_bfloat16 hy = __float2bfloat16(y);
    __nv_bfloat162 hp; hp.x = hx; hp.y = hy;
    hi = *(uint32_t*)&hp;
    lo = packbf2(x - __bfloat162float(hx), y - __bfloat162float(hy));
}

__device__ __forceinline__ void mma16816(float* d, const uint32_t* a, const uint32_t* b)
{
    asm volatile(
        "mma.sync.aligned.m16n8k16.row.col.f32.bf16.bf16.f32 "
        "{%0,%1,%2,%3}, {%4,%5,%6,%7}, {%8,%9}, {%0,%1,%2,%3};"
        : "+f"(d[0]), "+f"(d[1]), "+f"(d[2]), "+f"(d[3])
        : "r"(a[0]), "r"(a[1]), "r"(a[2]), "r"(a[3]), "r"(b[0]), "r"(b[1]));
}

// vector reductions to gmem
__device__ __forceinline__ void red4(float* addr, float a, float b, float c, float d)
{
    asm volatile("red.global.add.v4.f32 [%0], {%1, %2, %3, %4};"
                 :: "l"(addr), "f"(a), "f"(b), "f"(c), "f"(d) : "memory");
}
__device__ __forceinline__ void red2(float* addr, float a, float b)
{
    asm volatile("red.global.add.v2.f32 [%0], {%1, %2};"
                 :: "l"(addr), "f"(a), "f"(b) : "memory");
}

// ---------------------------------------------------------------------------
// Index dtype detection (int64 values < 125000 -> odd 32-bit words all zero)
// ---------------------------------------------------------------------------
__global__ void k_detect(const unsigned int* __restrict__ words)
{
    int all_hi_zero = 1;
    for (int k = 0; k < 64; ++k)
        if (words[2 * k + 1] != 0u) { all_hi_zero = 0; break; }
    g_idx64 = all_hi_zero;
}
__device__ __forceinline__ long long load_idx(const void* p, int i, int is64)
{
    return is64 ? ((const long long*)p)[i] : (long long)((const int*)p)[i];
}

// ---------------------------------------------------------------------------
// Zero scatter targets (graph replays -> re-zero every launch)
// ---------------------------------------------------------------------------
__global__ void k_zero(int n4_hsum, int n4_ct)
{
    int i = blockIdx.x * blockDim.x + threadIdx.x;
    float4 z = make_float4(0.f, 0.f, 0.f, 0.f);
    if (i < n4_hsum)              ((float4*)g_hsum)[i] = z;
    else if (i < n4_hsum + n4_ct) ((float4*)g_ctilde)[i - n4_hsum] = z;
}

// ---------------------------------------------------------------------------
// Pack biases + W_el bf16 hi/lo pair image ([g2][c], B-fragment-ready)
// ---------------------------------------------------------------------------
__global__ void k_pack(const float* __restrict__ bWf, const float* __restrict__ bf,
                       const float* __restrict__ bWi, const float* __restrict__ bi,
                       const float* __restrict__ bWu, const float* __restrict__ bu,
                       const float* __restrict__ bWo, const float* __restrict__ bo,
                       const float* __restrict__ W_el)
{
    int id = blockIdx.x * blockDim.x + threadIdx.x;
    if (id < 512) {
        int q = id >> 7, j = id & 127;
        const float* bW = (q == 0) ? bWf : (q == 1) ? bWi : (q == 2) ? bWu : bWo;
        const float* bb = (q == 0) ? bf  : (q == 1) ? bi  : (q == 2) ? bu  : bo;
        g_bias[id] = bW[j] + bb[j];
    }
    if (id < 32 * 128) {        // W_el pairs: id = g2*128 + c
        int g2 = id >> 7, c = id & 127;
        float w0 = W_el[c * 64 + 2 * g2];
        float w1 = W_el[c * 64 + 2 * g2 + 1];
        uint32_t hi, lo;
        split_pair(w0, w1, hi, lo);
        g_Welh2[id] = hi;
        g_Well2[id] = lo;
    }
}

// ---------------------------------------------------------------------------
// Pack gate weights into bf16 hi/lo k-pair images: g_B?2[k2*512 + j]
// ---------------------------------------------------------------------------
__global__ void k_packB(const float* __restrict__ Wf, const float* __restrict__ Wi,
                        const float* __restrict__ Wu, const float* __restrict__ Wo)
{
    int id = blockIdx.x * blockDim.x + threadIdx.x;   // 0 .. 128*512-1
    if (id >= 128 * 512) return;
    int k2 = id >> 9;
    int j  = id & 511;
    int q = j >> 7, jj = j & 127;
    const float* W = (q == 0) ? Wf : (q == 1) ? Wi : (q == 2) ? Wu : Wo;
    float w0 = W[jj * 256 + 2 * k2];
    float w1 = W[jj * 256 + 2 * k2 + 1];
    uint32_t hi, lo;
    split_pair(w0, w1, hi, lo);
    g_Bh2[id] = hi;
    g_Bl2[id] = lo;
}

// ---------------------------------------------------------------------------
// Edge-message GEMM (mma.sync bf16 3-term) + scatter.
// Per block: 128 edges x 128 channels, K = 64.
//   feat[e,g]  = sfeat*dfeat + W_eoh[g,t] + b_eoh[g]   -> smem bf16 hi/lo pairs
//   edge_w     = feat @ W_el^T  (mma, B = W_el directly: col-major [c][g])
//   epilogue:    h_sum[dst, c]     += (edge_w + b_el) * h_src   (v2 red)
//                h_sum[dst, 128+c] += embed                      (v4 red)
// ---------------------------------------------------------------------------
struct EdgeSm {
    uint32_t Ah[32 * 132];     // feat hi pairs  [g2][edge]
    uint32_t Al[32 * 132];     // feat lo pairs
    uint32_t Bh[32 * 132];     // W_el hi pairs  [g2][c]
    uint32_t Bl[32 * 132];     // W_el lo pairs
    int   sdst[128];
    int   stype[128];
    float sWeoh[192];
    float sbeoh[64];
    float sbel[128];
};

__global__ __launch_bounds__(256, 2) void k_edgemm(
    const float* __restrict__ h_src, const float* __restrict__ embed,
    const float* __restrict__ sfeat, const float* __restrict__ dfeat,
    const float* __restrict__ W_eoh, const float* __restrict__ b_eoh,
    const float* __restrict__ b_el,
    const void*  __restrict__ etype, const void*  __restrict__ dsti,
    int E)
{
    extern __shared__ char smraw[];
    EdgeSm* sm = (EdgeSm*)smraw;

    const int tid  = threadIdx.x;
    const int e0   = blockIdx.x * 128;
    const int is64 = g_idx64;

    // ---- stage indices / params / W_el pair image -----------------------
    if (tid < 128) {
        int e = e0 + tid;
        if (e < E) {
            sm->stype[tid] = (int)load_idx(etype, e, is64);
            sm->sdst [tid] = (int)load_idx(dsti,  e, is64);
        } else {
            sm->stype[tid] = 0;
            sm->sdst [tid] = -1;
        }
        sm->sbel[tid] = b_el[tid];
    }
    if (tid < 192) sm->sWeoh[tid] = W_eoh[tid];
    if (tid < 64)  sm->sbeoh[tid] = b_eoh[tid];

#pragma unroll
    for (int r = 0; r < 16; ++r) {
        int idx = tid + 256 * r;            // 0..4095 : g2*128 + c
        int g2 = idx >> 7, c = idx & 127;
        sm->Bh[g2 * 132 + c] = g_Welh2[idx];
        sm->Bl[g2 * 132 + c] = g_Well2[idx];
    }
    __syncthreads();

    // ---- compute feat, write bf16 hi/lo pairs into Ah/Al ----------------
    {
        const int el = tid & 127;
        const int g0 = (tid >> 7) * 4;
        const int e  = e0 + el;
        const int t  = sm->stype[el];
        const bool ok = (e < E);
#pragma unroll
        for (int r = 0; r < 8; ++r) {
            int g = g0 + r * 8;
            float4 sv = make_float4(0.f, 0.f, 0.f, 0.f);
            float4 dv = make_float4(0.f, 0.f, 0.f, 0.f);
            if (ok) {
                sv = *(const float4*)&sfeat[(size_t)e * 64 + g];
                dv = *(const float4*)&dfeat[(size_t)e * 64 + g];
            }
            float f0 = fmaf(sv.x, dv.x, sm->sWeoh[(g + 0) * 3 + t] + sm->sbeoh[g + 0]);
            float f1 = fmaf(sv.y, dv.y, sm->sWeoh[(g + 1) * 3 + t] + sm->sbeoh[g + 1]);
            float f2 = fmaf(sv.z, dv.z, sm->sWeoh[(g + 2) * 3 + t] + sm->sbeoh[g + 2]);
            float f3 = fmaf(sv.w, dv.w, sm->sWeoh[(g + 3) * 3 + t] + sm->sbeoh[g + 3]);
            uint32_t hi, lo;
            const int g2 = g >> 1;
            split_pair(f0, f1, hi, lo);
            sm->Ah[g2 * 132 + el] = hi;
            sm->Al[g2 * 132 + el] = lo;
            split_pair(f2, f3, hi, lo);
            sm->Ah[(g2 + 1) * 132 + el] = hi;
            sm->Al[(g2 + 1) * 132 + el] = lo;
        }
    }
    __syncthreads();

    // ---- mma: 8 warps, warp tile 64x32, K = 64 (4 chunks of 16) ---------
    const int lane = tid & 31;
    const int wid  = tid >> 5;
    const int wm   = (wid >> 2) * 64;
    const int wj   = (wid & 3) * 32;
    const int fr   = lane >> 2;
    const int fq   = lane & 3;

    float acc[4][4][4];
#pragma unroll
    for (int i = 0; i < 4; ++i)
#pragma unroll
        for (int j = 0; j < 4; ++j)
#pragma unroll
            for (int r = 0; r < 4; ++r) acc[i][j][r] = 0.f;

#pragma unroll
    for (int c8 = 0; c8 < 32; c8 += 8) {
        uint32_t bh[4][2], bl[4][2];
#pragma unroll
        for (int j = 0; j < 4; ++j) {
            const int col = wj + j * 8 + fr;
            bh[j][0] = sm->Bh[(c8 + fq) * 132 + col];
            bh[j][1] = sm->Bh[(c8 + fq + 4) * 132 + col];
            bl[j][0] = sm->Bl[(c8 + fq) * 132 + col];
            bl[j][1] = sm->Bl[(c8 + fq + 4) * 132 + col];
        }
#pragma unroll
        for (int i = 0; i < 4; ++i) {
            const int row = wm + i * 16 + fr;
            uint32_t ah[4] = { sm->Ah[(c8 + fq) * 132 + row],
                               sm->Ah[(c8 + fq) * 132 + row + 8],
                               sm->Ah[(c8 + fq + 4) * 132 + row],
                               sm->Ah[(c8 + fq + 4) * 132 + row + 8] };
            uint32_t al[4] = { sm->Al[(c8 + fq) * 132 + row],
                               sm->Al[(c8 + fq) * 132 + row + 8],
                               sm->Al[(c8 + fq + 4) * 132 + row],
                               sm->Al[(c8 + fq + 4) * 132 + row + 8] };
#pragma unroll
            for (int j = 0; j < 4; ++j) {
                mma16816(acc[i][j], ah, bh[j]);
                mma16816(acc[i][j], ah, bl[j]);
                mma16816(acc[i][j], al, bh[j]);
            }
        }
    }

    // ---- epilogue A: (edge_w + b_el) * h_src -> v2 reductions -----------
#pragma unroll
    for (int i = 0; i < 4; ++i) {
#pragma unroll
        for (int half = 0; half < 2; ++half) {
            const int le  = wm + i * 16 + fr + half * 8;
            const int dst = sm->sdst[le];
            if (dst < 0) continue;
            const float* hrow = &h_src[(size_t)(e0 + le) * 128];
            float* orow = &g_hsum[(size_t)dst * 256];
#pragma unroll
            for (int j = 0; j < 4; ++j) {
                const int c = wj + j * 8 + fq * 2;
                float2 h = *(const float2*)&hrow[c];
                float w0 = acc[i][j][half * 2 + 0] + sm->sbel[c];
                float w1 = acc[i][j][half * 2 + 1] + sm->sbel[c + 1];
                red2(&orow[c], w0 * h.x, w1 * h.y);
            }
        }
    }

    // ---- epilogue B: embed -> v4 reductions -----------------------------
    {
        const int tx = tid & 15;
        const int ty = tid >> 4;
#pragma unroll
        for (int i = 0; i < 8; ++i) {
            const int le  = ty * 8 + i;
            const int dst = sm->sdst[le];
            if (dst < 0) continue;
            const int e = e0 + le;
            float4 m0 = *(const float4*)&embed[(size_t)e * 128 + tx * 8];
            float4 m1 = *(const float4*)&embed[(size_t)e * 128 + tx * 8 + 4];
            float* b = &g_hsum[(size_t)dst * 256 + 128 + tx * 8];
            red4(b,     m0.x, m0.y, m0.z, m0.w);
            red4(b + 4, m1.x, m1.y, m1.z, m1.w);
        }
    }
}

// ---------------------------------------------------------------------------
// Gate GEMM via mma.sync bf16 3-term split, double-buffered (1 sync / chunk):
//   g_gates[N,512] = act( h_sum[N,256] @ B[256,512] + bias )
// grid (4, ceil(N/128)); 8 warps, warp tile 64x32, k-step 16 (16 chunks).
// ---------------------------------------------------------------------------
__global__ __launch_bounds__(256) void k_mgemm(int N)
{
    __shared__ uint32_t Ah2[2][8][132];
    __shared__ uint32_t Al2[2][8][132];
    __shared__ uint32_t Bh2[2][8][132];
    __shared__ uint32_t Bl2[2][8][132];

    const int tid  = threadIdx.x;
    const int lane = tid & 31;
    const int wid  = tid >> 5;
    const int m0   = blockIdx.y * 128;
    const int j0   = blockIdx.x * 128;
    const int wm   = (wid >> 2) * 64;
    const int wj   = (wid & 3) * 32;

    float acc[4][4][4];
#pragma unroll
    for (int i = 0; i < 4; ++i)
#pragma unroll
        for (int j = 0; j < 4; ++j)
#pragma unroll
            for (int r = 0; r < 4; ++r) acc[i][j][r] = 0.f;

    // staging roles
    const int  arow = tid >> 1;
    const int  akq  = tid & 1;             // which 8-K half
    const bool arok = (m0 + arow) < N;
    const int  bbr  = tid >> 5;            // B k2 row 0..7
    const int  bjc  = (tid & 31) * 4;      // B col group

    float4 pa0, pa1;
    uint4  pbh, pbl;

    auto prefetch = [&](int kc) {
        pa0 = make_float4(0.f, 0.f, 0.f, 0.f);
        pa1 = pa0;
        if (arok) {
            const float* src = &g_hsum[(size_t)(m0 + arow) * 256 + kc * 16 + akq * 8];
            pa0 = *(const float4*)(src);
            pa1 = *(const float4*)(src + 4);
        }
        pbh = *(const uint4*)&g_Bh2[(size_t)(kc * 8 + bbr) * 512 + j0 + bjc];
        pbl = *(const uint4*)&g_Bl2[(size_t)(kc * 8 + bbr) * 512 + j0 + bjc];
    };
    auto store_chunk = [&](int buf) {
        const int kb = akq * 4;
        split_pair(pa0.x, pa0.y, Ah2[buf][kb + 0][arow], Al2[buf][kb + 0][arow]);
        split_pair(pa0.z, pa0.w, Ah2[buf][kb + 1][arow], Al2[buf][kb + 1][arow]);
        split_pair(pa1.x, pa1.y, Ah2[buf][kb + 2][arow], Al2[buf][kb + 2][arow]);
        split_pair(pa1.z, pa1.w, Ah2[buf][kb + 3][arow], Al2[buf][kb + 3][arow]);
        *(uint4*)&Bh2[buf][bbr][bjc] = pbh;
        *(uint4*)&Bl2[buf][bbr][bjc] = pbl;
    };

    prefetch(0);
    store_chunk(0);
    __syncthreads();

    const int fr = lane >> 2;     // fragment row/col selector
    const int fk = lane & 3;      // k2 selector

    for (int kc = 0; kc < 16; ++kc) {
        const int cur = kc & 1;
        if (kc < 15) prefetch(kc + 1);

        // ---- mma on current chunk --------------------------------------
        uint32_t bh[4][2], bl[4][2];
#pragma unroll
        for (int j = 0; j < 4; ++j) {
            const int col = wj + j * 8 + fr;
            bh[j][0] = Bh2[cur][fk][col];
            bh[j][1] = Bh2[cur][fk + 4][col];
            bl[j][0] = Bl2[cur][fk][col];
            bl[j][1] = Bl2[cur][fk + 4][col];
        }
#pragma unroll
        for (int i = 0; i < 4; ++i) {
            const int row = wm + i * 16 + fr;
            uint32_t ah[4] = { Ah2[cur][fk][row], Ah2[cur][fk][row + 8],
                               Ah2[cur][fk + 4][row], Ah2[cur][fk + 4][row + 8] };
            uint32_t al[4] = { Al2[cur][fk][row], Al2[cur][fk][row + 8],
                               Al2[cur][fk + 4][row], Al2[cur][fk + 4][row + 8] };
#pragma unroll
            for (int j = 0; j < 4; ++j) {
                mma16816(acc[i][j], ah, bh[j]);
                mma16816(acc[i][j], ah, bl[j]);
                mma16816(acc[i][j], al, bh[j]);
            }
        }

        if (kc < 15) store_chunk(cur ^ 1);
        __syncthreads();
    }

    // ---- epilogue: bias + activation + store ----------------------------
    const int q = blockIdx.x;   // gate: 0=f 1=i 2=u(tanh) 3=o
#pragma unroll
    for (int j = 0; j < 4; ++j) {
        const int c = j0 + wj + j * 8 + (lane & 3) * 2;
        const float b0 = g_bias[c], b1 = g_bias[c + 1];
#pragma unroll
        for (int i = 0; i < 4; ++i) {
            const int mr = m0 + wm + i * 16 + (lane >> 2);
#pragma unroll
            for (int half = 0; half < 2; ++half) {
                const int m = mr + half * 8;
                if (m >= N) continue;
                float v0 = acc[i][j][half * 2 + 0] + b0;
                float v1 = acc[i][j][half * 2 + 1] + b1;
                float2 o;
                if (q == 2) { o.x = tanhf(v0); o.y = tanhf(v1); }
                else        { o.x = 1.f / (1.f + expf(-v0)); o.y = 1.f / (1.f + expf(-v1)); }
                *(float2*)&g_gates[(size_t)m * 512 + c] = o;
            }
        }
    }
}

// ---------------------------------------------------------------------------
// c_tilde[d, h] += f[d,h] * c_src[e,h]   (one v4 reduction per thread)
// ---------------------------------------------------------------------------
__global__ void k_scatter(const float* __restrict__ c_src,
                          const void* __restrict__ dsti, int E)
{
    int id = blockIdx.x * blockDim.x + threadIdx.x;
    int e  = id >> 5;
    if (e >= E) return;
    int h4 = (id & 31) * 4;
    long long dst = load_idx(dsti, e, g_idx64);
    float4 f = *(const float4*)&g_gates[(size_t)dst * 512 + h4];
    float4 c = *(const float4*)&c_src[(size_t)e * 128 + h4];
    red4(&g_ctilde[(size_t)dst * 128 + h4],
         f.x * c.x, f.y * c.y, f.z * c.z, f.w * c.w);
}

// ---------------------------------------------------------------------------
// Finalize: c = i*u + c_tilde ; h = o*tanh(c) ; out = [h | c]
// ---------------------------------------------------------------------------
__global__ void k_final(float* __restrict__ out, int N)
{
    int id = blockIdx.x * blockDim.x + threadIdx.x;
    int n  = id >> 5;
    if (n >= N) return;
    int h4 = (id & 31) * 4;
    const float* gr = &g_gates[(size_t)n * 512];
    float4 ig = *(const float4*)&gr[128 + h4];
    float4 ug = *(const float4*)&gr[256 + h4];
    float4 og = *(const float4*)&gr[384 + h4];
    float4 ct = *(const float4*)&g_ctilde[(size_t)n * 128 + h4];
    float4 c, h;
    c.x = fmaf(ig.x, ug.x, ct.x);  h.x = og.x * tanhf(c.x);
    c.y = fmaf(ig.y, ug.y, ct.y);  h.y = og.y * tanhf(c.y);
    c.z = fmaf(ig.z, ug.z, ct.z);  h.z = og.z * tanhf(c.z);
    c.w = fmaf(ig.w, ug.w, ct.w);  h.w = og.w * tanhf(c.w);
    *(float4*)&out[(size_t)n * 256 + h4]       = h;
    *(float4*)&out[(size_t)n * 256 + 128 + h4] = c;
}

// ---------------------------------------------------------------------------
// Launch
// ---------------------------------------------------------------------------
extern "C" void kernel_launch(void* const* d_in, const int* in_sizes, int n_in,
                              void* d_out, int out_size)
{
    const float* h_src = (const float*)d_in[0];
    const float* c_src = (const float*)d_in[1];
    const float* embed = (const float*)d_in[2];
    const float* sfeat = (const float*)d_in[3];
    const float* dfeat = (const float*)d_in[4];
    const float* Wf  = (const float*)d_in[5];
    const float* bWf = (const float*)d_in[6];
    const float* bf  = (const float*)d_in[7];
    const float* Wi  = (const float*)d_in[8];
    const float* bWi = (const float*)d_in[9];
    const float* bi  = (const float*)d_in[10];
    const float* Wu  = (const float*)d_in[11];
    const float* bWu = (const float*)d_in[12];
    const float* bu  = (const float*)d_in[13];
    const float* Wo  = (const float*)d_in[14];
    const float* bWo = (const float*)d_in[15];
    const float* bo  = (const float*)d_in[16];
    const float* W_eoh = (const float*)d_in[17];
    const float* b_eoh = (const float*)d_in[18];
    const float* W_el  = (const float*)d_in[19];
    const float* b_el  = (const float*)d_in[20];
    const void*  etype = d_in[21];
    const void*  dsti  = d_in[22];

    const int E = in_sizes[0] / 128;
    const int N = out_size   / 256;

    cudaFuncSetAttribute(k_edgemm, cudaFuncAttributeMaxDynamicSharedMemorySize,
                         (int)sizeof(EdgeSm));

    // 1) index dtype probe
    k_detect<<<1, 1>>>((const unsigned int*)dsti);

    // 2) zero scatter targets
    const int n4h = N * 64, n4c = N * 32;
    k_zero<<<(n4h + n4c + 255) / 256, 256>>>(n4h, n4c);

    // 3) pack biases / W_el pair image / bf16 gate-weight pair images
    k_pack<<<32, 256>>>(bWf, bf, bWi, bi, bWu, bu, bWo, bo, W_el);
    k_packB<<<256, 256>>>(Wf, Wi, Wu, Wo);

    // 4) edge-message GEMM (tensor) + scatter into h_sum
    k_edgemm<<<(E + 127) / 128, 256, sizeof(EdgeSm)>>>(
        h_src, embed, sfeat, dfeat, W_eoh, b_eoh, b_el, etype, dsti, E);

    // 5) gate GEMM (mma.sync bf16 3-term, double-buffered) + activations
    dim3 gg(4, (N + 127) / 128);
    k_mgemm<<<gg, 256>>>(N);

    // 6) c_tilde scatter (needs activated f)
    long long scat = (long long)E * 32;
    k_scatter<<<(int)((scat + 255) / 256), 256>>>(c_src, dsti, E);

    // 7) finalize
    k_final<<<(N * 32 + 255) / 256, 256>>>((float*)d_out, N);
}

// round 9
// speedup vs baseline: 2.5705x; 1.0074x over previous
#include <cuda_runtime.h>
#include <cuda_bf16.h>
#include <math.h>
#include <stdint.h>

// ---------------------------------------------------------------------------
// Problem constants
// ---------------------------------------------------------------------------
#define MAXN 125000
#define MAXE 500000

// Scratch (device globals -- no allocation allowed)
__device__ float g_hsum  [(size_t)MAXN * 256];   // [N, H+X] segment sum
__device__ float g_gates [(size_t)MAXN * 512];   // activated gates f,i,u,o each [N,128]
__device__ float g_csum  [(size_t)MAXN * 128];   // segment_sum(c_src)  [N, H]
__device__ float g_bias  [512];                  // bW* + b*
__device__ uint32_t g_Bh2[128 * 512];            // gate W hi: bf16x2 pairs along K  [k2][j]
__device__ uint32_t g_Bl2[128 * 512];            // gate W lo
__device__ uint32_t g_Welh2[32 * 128];           // W_el hi: bf16x2 pairs along g  [g2][c]
__device__ uint32_t g_Well2[32 * 128];           // W_el lo
__device__ int   g_idx64;

// ---------------------------------------------------------------------------
// Helpers
// ---------------------------------------------------------------------------
__device__ __forceinline__ uint32_t packbf2(float x, float y)
{
    __nv_bfloat162 p = __floats2bfloat162_rn(x, y);
    return *(uint32_t*)&p;
}

// split (x, y) into bf16x2 hi + bf16x2 lo words
__device__ __forceinline__ void split_pair(float x, float y, uint32_t& hi, uint32_t& lo)
{
    __nv_bfloat16 hx = __float2bfloat16(x);
    __nv_bfloat16 hy = __float2bfloat16(y);
    __nv_bfloat162 hp; hp.x = hx; hp.y = hy;
    hi = *(uint32_t*)&hp;
    lo = packbf2(x - __bfloat162float(hx), y - __bfloat162float(hy));
}

__device__ __forceinline__ void mma16816(float* d, const uint32_t* a, const uint32_t* b)
{
    asm volatile(
        "mma.sync.aligned.m16n8k16.row.col.f32.bf16.bf16.f32 "
        "{%0,%1,%2,%3}, {%4,%5,%6,%7}, {%8,%9}, {%0,%1,%2,%3};"
        : "+f"(d[0]), "+f"(d[1]), "+f"(d[2]), "+f"(d[3])
        : "r"(a[0]), "r"(a[1]), "r"(a[2]), "r"(a[3]), "r"(b[0]), "r"(b[1]));
}

// vector reductions to gmem
__device__ __forceinline__ void red4(float* addr, float a, float b, float c, float d)
{
    asm volatile("red.global.add.v4.f32 [%0], {%1, %2, %3, %4};"
                 :: "l"(addr), "f"(a), "f"(b), "f"(c), "f"(d) : "memory");
}
__device__ __forceinline__ void red2(float* addr, float a, float b)
{
    asm volatile("red.global.add.v2.f32 [%0], {%1, %2};"
                 :: "l"(addr), "f"(a), "f"(b) : "memory");
}

// ---------------------------------------------------------------------------
// Index dtype detection (int64 values < 125000 -> odd 32-bit words all zero)
// ---------------------------------------------------------------------------
__global__ void k_detect(const unsigned int* __restrict__ words)
{
    int all_hi_zero = 1;
    for (int k = 0; k < 64; ++k)
        if (words[2 * k + 1] != 0u) { all_hi_zero = 0; break; }
    g_idx64 = all_hi_zero;
}
__device__ __forceinline__ long long load_idx(const void* p, int i, int is64)
{
    return is64 ? ((const long long*)p)[i] : (long long)((const int*)p)[i];
}

// ---------------------------------------------------------------------------
// Zero scatter targets (graph replays -> re-zero every launch)
// ---------------------------------------------------------------------------
__global__ void k_zero(int n4_hsum, int n4_cs)
{
    int i = blockIdx.x * blockDim.x + threadIdx.x;
    float4 z = make_float4(0.f, 0.f, 0.f, 0.f);
    if (i < n4_hsum)              ((float4*)g_hsum)[i] = z;
    else if (i < n4_hsum + n4_cs) ((float4*)g_csum)[i - n4_hsum] = z;
}

// ---------------------------------------------------------------------------
// Pack biases + W_el bf16 hi/lo pair image ([g2][c], B-fragment-ready)
// ---------------------------------------------------------------------------
__global__ void k_pack(const float* __restrict__ bWf, const float* __restrict__ bf,
                       const float* __restrict__ bWi, const float* __restrict__ bi,
                       const float* __restrict__ bWu, const float* __restrict__ bu,
                       const float* __restrict__ bWo, const float* __restrict__ bo,
                       const float* __restrict__ W_el)
{
    int id = blockIdx.x * blockDim.x + threadIdx.x;
    if (id < 512) {
        int q = id >> 7, j = id & 127;
        const float* bW = (q == 0) ? bWf : (q == 1) ? bWi : (q == 2) ? bWu : bWo;
        const float* bb = (q == 0) ? bf  : (q == 1) ? bi  : (q == 2) ? bu  : bo;
        g_bias[id] = bW[j] + bb[j];
    }
    if (id < 32 * 128) {        // W_el pairs: id = g2*128 + c
        int g2 = id >> 7, c = id & 127;
        float w0 = W_el[c * 64 + 2 * g2];
        float w1 = W_el[c * 64 + 2 * g2 + 1];
        uint32_t hi, lo;
        split_pair(w0, w1, hi, lo);
        g_Welh2[id] = hi;
        g_Well2[id] = lo;
    }
}

// ---------------------------------------------------------------------------
// Pack gate weights into bf16 hi/lo k-pair images: g_B?2[k2*512 + j]
// ---------------------------------------------------------------------------
__global__ void k_packB(const float* __restrict__ Wf, const float* __restrict__ Wi,
                        const float* __restrict__ Wu, const float* __restrict__ Wo)
{
    int id = blockIdx.x * blockDim.x + threadIdx.x;   // 0 .. 128*512-1
    if (id >= 128 * 512) return;
    int k2 = id >> 9;
    int j  = id & 511;
    int q = j >> 7, jj = j & 127;
    const float* W = (q == 0) ? Wf : (q == 1) ? Wi : (q == 2) ? Wu : Wo;
    float w0 = W[jj * 256 + 2 * k2];
    float w1 = W[jj * 256 + 2 * k2 + 1];
    uint32_t hi, lo;
    split_pair(w0, w1, hi, lo);
    g_Bh2[id] = hi;
    g_Bl2[id] = lo;
}

// ---------------------------------------------------------------------------
// Edge-message GEMM (mma.sync bf16 3-term) + scatter.
// Per block: 128 edges x 128 channels, K = 64.
//   feat[e,g]  = sfeat*dfeat + W_eoh[g,t] + b_eoh[g]   -> smem bf16 hi/lo pairs
//   edge_w     = feat @ W_el^T  (mma, B = W_el directly: col-major [c][g])
//   epilogue A:  h_sum[dst, c]     += (edge_w + b_el) * h_src   (v2 red)
//   epilogue B:  h_sum[dst, 128+c] += embed                      (v4 red)
//                c_sum[dst, c]     += c_src                      (v4 red)
// ---------------------------------------------------------------------------
struct EdgeSm {
    uint32_t Ah[32 * 132];     // feat hi pairs  [g2][edge]
    uint32_t Al[32 * 132];     // feat lo pairs
    uint32_t Bh[32 * 132];     // W_el hi pairs  [g2][c]
    uint32_t Bl[32 * 132];     // W_el lo pairs
    int   sdst[128];
    int   stype[128];
    float sWeoh[192];
    float sbeoh[64];
    float sbel[128];
};

__global__ __launch_bounds__(256, 2) void k_edgemm(
    const float* __restrict__ h_src, const float* __restrict__ embed,
    const float* __restrict__ c_src,
    const float* __restrict__ sfeat, const float* __restrict__ dfeat,
    const float* __restrict__ W_eoh, const float* __restrict__ b_eoh,
    const float* __restrict__ b_el,
    const void*  __restrict__ etype, const void*  __restrict__ dsti,
    int E)
{
    extern __shared__ char smraw[];
    EdgeSm* sm = (EdgeSm*)smraw;

    const int tid  = threadIdx.x;
    const int e0   = blockIdx.x * 128;
    const int is64 = g_idx64;

    // ---- stage indices / params / W_el pair image -----------------------
    if (tid < 128) {
        int e = e0 + tid;
        if (e < E) {
            sm->stype[tid] = (int)load_idx(etype, e, is64);
            sm->sdst [tid] = (int)load_idx(dsti,  e, is64);
        } else {
            sm->stype[tid] = 0;
            sm->sdst [tid] = -1;
        }
        sm->sbel[tid] = b_el[tid];
    }
    if (tid < 192) sm->sWeoh[tid] = W_eoh[tid];
    if (tid < 64)  sm->sbeoh[tid] = b_eoh[tid];

#pragma unroll
    for (int r = 0; r < 16; ++r) {
        int idx = tid + 256 * r;            // 0..4095 : g2*128 + c
        int g2 = idx >> 7, c = idx & 127;
        sm->Bh[g2 * 132 + c] = g_Welh2[idx];
        sm->Bl[g2 * 132 + c] = g_Well2[idx];
    }
    __syncthreads();

    // ---- compute feat, write bf16 hi/lo pairs into Ah/Al ----------------
    {
        const int el = tid & 127;
        const int g0 = (tid >> 7) * 4;
        const int e  = e0 + el;
        const int t  = sm->stype[el];
        const bool ok = (e < E);
#pragma unroll
        for (int r = 0; r < 8; ++r) {
            int g = g0 + r * 8;
            float4 sv = make_float4(0.f, 0.f, 0.f, 0.f);
            float4 dv = make_float4(0.f, 0.f, 0.f, 0.f);
            if (ok) {
                sv = *(const float4*)&sfeat[(size_t)e * 64 + g];
                dv = *(const float4*)&dfeat[(size_t)e * 64 + g];
            }
            float f0 = fmaf(sv.x, dv.x, sm->sWeoh[(g + 0) * 3 + t] + sm->sbeoh[g + 0]);
            float f1 = fmaf(sv.y, dv.y, sm->sWeoh[(g + 1) * 3 + t] + sm->sbeoh[g + 1]);
            float f2 = fmaf(sv.z, dv.z, sm->sWeoh[(g + 2) * 3 + t] + sm->sbeoh[g + 2]);
            float f3 = fmaf(sv.w, dv.w, sm->sWeoh[(g + 3) * 3 + t] + sm->sbeoh[g + 3]);
            uint32_t hi, lo;
            const int g2 = g >> 1;
            split_pair(f0, f1, hi, lo);
            sm->Ah[g2 * 132 + el] = hi;
            sm->Al[g2 * 132 + el] = lo;
            split_pair(f2, f3, hi, lo);
            sm->Ah[(g2 + 1) * 132 + el] = hi;
            sm->Al[(g2 + 1) * 132 + el] = lo;
        }
    }
    __syncthreads();

    // ---- mma: 8 warps, warp tile 64x32, K = 64 (4 chunks of 16) ---------
    const int lane = tid & 31;
    const int wid  = tid >> 5;
    const int wm   = (wid >> 2) * 64;
    const int wj   = (wid & 3) * 32;
    const int fr   = lane >> 2;
    const int fq   = lane & 3;

    float acc[4][4][4];
#pragma unroll
    for (int i = 0; i < 4; ++i)
#pragma unroll
        for (int j = 0; j < 4; ++j)
#pragma unroll
            for (int r = 0; r < 4; ++r) acc[i][j][r] = 0.f;

#pragma unroll
    for (int c8 = 0; c8 < 32; c8 += 8) {
        uint32_t bh[4][2], bl[4][2];
#pragma unroll
        for (int j = 0; j < 4; ++j) {
            const int col = wj + j * 8 + fr;
            bh[j][0] = sm->Bh[(c8 + fq) * 132 + col];
            bh[j][1] = sm->Bh[(c8 + fq + 4) * 132 + col];
            bl[j][0] = sm->Bl[(c8 + fq) * 132 + col];
            bl[j][1] = sm->Bl[(c8 + fq + 4) * 132 + col];
        }
#pragma unroll
        for (int i = 0; i < 4; ++i) {
            const int row = wm + i * 16 + fr;
            uint32_t ah[4] = { sm->Ah[(c8 + fq) * 132 + row],
                               sm->Ah[(c8 + fq) * 132 + row + 8],
                               sm->Ah[(c8 + fq + 4) * 132 + row],
                               sm->Ah[(c8 + fq + 4) * 132 + row + 8] };
            uint32_t al[4] = { sm->Al[(c8 + fq) * 132 + row],
                               sm->Al[(c8 + fq) * 132 + row + 8],
                               sm->Al[(c8 + fq + 4) * 132 + row],
                               sm->Al[(c8 + fq + 4) * 132 + row + 8] };
#pragma unroll
            for (int j = 0; j < 4; ++j) {
                mma16816(acc[i][j], ah, bh[j]);
                mma16816(acc[i][j], ah, bl[j]);
                mma16816(acc[i][j], al, bh[j]);
            }
        }
    }

    // ---- epilogue A: (edge_w + b_el) * h_src -> v2 reductions -----------
#pragma unroll
    for (int i = 0; i < 4; ++i) {
#pragma unroll
        for (int half = 0; half < 2; ++half) {
            const int le  = wm + i * 16 + fr + half * 8;
            const int dst = sm->sdst[le];
            if (dst < 0) continue;
            const float* hrow = &h_src[(size_t)(e0 + le) * 128];
            float* orow = &g_hsum[(size_t)dst * 256];
#pragma unroll
            for (int j = 0; j < 4; ++j) {
                const int c = wj + j * 8 + fq * 2;
                float2 h = *(const float2*)&hrow[c];
                float w0 = acc[i][j][half * 2 + 0] + sm->sbel[c];
                float w1 = acc[i][j][half * 2 + 1] + sm->sbel[c + 1];
                red2(&orow[c], w0 * h.x, w1 * h.y);
            }
        }
    }

    // ---- epilogue B: embed + c_src -> v4 reductions ---------------------
    {
        const int tx = tid & 15;
        const int ty = tid >> 4;
#pragma unroll
        for (int i = 0; i < 8; ++i) {
            const int le  = ty * 8 + i;
            const int dst = sm->sdst[le];
            if (dst < 0) continue;
            const int e = e0 + le;
            float4 m0 = *(const float4*)&embed[(size_t)e * 128 + tx * 8];
            float4 m1 = *(const float4*)&embed[(size_t)e * 128 + tx * 8 + 4];
            float* b = &g_hsum[(size_t)dst * 256 + 128 + tx * 8];
            red4(b,     m0.x, m0.y, m0.z, m0.w);
            red4(b + 4, m1.x, m1.y, m1.z, m1.w);
            float4 c0 = *(const float4*)&c_src[(size_t)e * 128 + tx * 8];
            float4 c1 = *(const float4*)&c_src[(size_t)e * 128 + tx * 8 + 4];
            float* cs = &g_csum[(size_t)dst * 128 + tx * 8];
            red4(cs,     c0.x, c0.y, c0.z, c0.w);
            red4(cs + 4, c1.x, c1.y, c1.z, c1.w);
        }
    }
}

// ---------------------------------------------------------------------------
// Gate GEMM via mma.sync bf16 3-term split, double-buffered (1 sync / chunk):
//   g_gates[N,512] = act( h_sum[N,256] @ B[256,512] + bias )
// grid (4, ceil(N/128)); 8 warps, warp tile 64x32, k-step 16 (16 chunks).
// ---------------------------------------------------------------------------
__global__ __launch_bounds__(256) void k_mgemm(int N)
{
    __shared__ uint32_t Ah2[2][8][132];
    __shared__ uint32_t Al2[2][8][132];
    __shared__ uint32_t Bh2[2][8][132];
    __shared__ uint32_t Bl2[2][8][132];

    const int tid  = threadIdx.x;
    const int lane = tid & 31;
    const int wid  = tid >> 5;
    const int m0   = blockIdx.y * 128;
    const int j0   = blockIdx.x * 128;
    const int wm   = (wid >> 2) * 64;
    const int wj   = (wid & 3) * 32;

    float acc[4][4][4];
#pragma unroll
    for (int i = 0; i < 4; ++i)
#pragma unroll
        for (int j = 0; j < 4; ++j)
#pragma unroll
            for (int r = 0; r < 4; ++r) acc[i][j][r] = 0.f;

    // staging roles
    const int  arow = tid >> 1;
    const int  akq  = tid & 1;             // which 8-K half
    const bool arok = (m0 + arow) < N;
    const int  bbr  = tid >> 5;            // B k2 row 0..7
    const int  bjc  = (tid & 31) * 4;      // B col group

    float4 pa0, pa1;
    uint4  pbh, pbl;

    auto prefetch = [&](int kc) {
        pa0 = make_float4(0.f, 0.f, 0.f, 0.f);
        pa1 = pa0;
        if (arok) {
            const float* src = &g_hsum[(size_t)(m0 + arow) * 256 + kc * 16 + akq * 8];
            pa0 = *(const float4*)(src);
            pa1 = *(const float4*)(src + 4);
        }
        pbh = *(const uint4*)&g_Bh2[(size_t)(kc * 8 + bbr) * 512 + j0 + bjc];
        pbl = *(const uint4*)&g_Bl2[(size_t)(kc * 8 + bbr) * 512 + j0 + bjc];
    };
    auto store_chunk = [&](int buf) {
        const int kb = akq * 4;
        split_pair(pa0.x, pa0.y, Ah2[buf][kb + 0][arow], Al2[buf][kb + 0][arow]);
        split_pair(pa0.z, pa0.w, Ah2[buf][kb + 1][arow], Al2[buf][kb + 1][arow]);
        split_pair(pa1.x, pa1.y, Ah2[buf][kb + 2][arow], Al2[buf][kb + 2][arow]);
        split_pair(pa1.z, pa1.w, Ah2[buf][kb + 3][arow], Al2[buf][kb + 3][arow]);
        *(uint4*)&Bh2[buf][bbr][bjc] = pbh;
        *(uint4*)&Bl2[buf][bbr][bjc] = pbl;
    };

    prefetch(0);
    store_chunk(0);
    __syncthreads();

    const int fr = lane >> 2;     // fragment row/col selector
    const int fk = lane & 3;      // k2 selector

    for (int kc = 0; kc < 16; ++kc) {
        const int cur = kc & 1;
        if (kc < 15) prefetch(kc + 1);

        // ---- mma on current chunk --------------------------------------
        uint32_t bh[4][2], bl[4][2];
#pragma unroll
        for (int j = 0; j < 4; ++j) {
            const int col = wj + j * 8 + fr;
            bh[j][0] = Bh2[cur][fk][col];
            bh[j][1] = Bh2[cur][fk + 4][col];
            bl[j][0] = Bl2[cur][fk][col];
            bl[j][1] = Bl2[cur][fk + 4][col];
        }
#pragma unroll
        for (int i = 0; i < 4; ++i) {
            const int row = wm + i * 16 + fr;
            uint32_t ah[4] = { Ah2[cur][fk][row], Ah2[cur][fk][row + 8],
                               Ah2[cur][fk + 4][row], Ah2[cur][fk + 4][row + 8] };
            uint32_t al[4] = { Al2[cur][fk][row], Al2[cur][fk][row + 8],
                               Al2[cur][fk + 4][row], Al2[cur][fk + 4][row + 8] };
#pragma unroll
            for (int j = 0; j < 4; ++j) {
                mma16816(acc[i][j], ah, bh[j]);
                mma16816(acc[i][j], ah, bl[j]);
                mma16816(acc[i][j], al, bh[j]);
            }
        }

        if (kc < 15) store_chunk(cur ^ 1);
        __syncthreads();
    }

    // ---- epilogue: bias + activation + store ----------------------------
    const int q = blockIdx.x;   // gate: 0=f 1=i 2=u(tanh) 3=o
#pragma unroll
    for (int j = 0; j < 4; ++j) {
        const int c = j0 + wj + j * 8 + (lane & 3) * 2;
        const float b0 = g_bias[c], b1 = g_bias[c + 1];
#pragma unroll
        for (int i = 0; i < 4; ++i) {
            const int mr = m0 + wm + i * 16 + (lane >> 2);
#pragma unroll
            for (int half = 0; half < 2; ++half) {
                const int m = mr + half * 8;
                if (m >= N) continue;
                float v0 = acc[i][j][half * 2 + 0] + b0;
                float v1 = acc[i][j][half * 2 + 1] + b1;
                float2 o;
                if (q == 2) { o.x = tanhf(v0); o.y = tanhf(v1); }
                else        { o.x = 1.f / (1.f + expf(-v0)); o.y = 1.f / (1.f + expf(-v1)); }
                *(float2*)&g_gates[(size_t)m * 512 + c] = o;
            }
        }
    }
}

// ---------------------------------------------------------------------------
// Finalize: c = i*u + f*c_sum ; h = o*tanh(c) ; out = [h | c]
// ---------------------------------------------------------------------------
__global__ void k_final(float* __restrict__ out, int N)
{
    int id = blockIdx.x * blockDim.x + threadIdx.x;
    int n  = id >> 5;
    if (n >= N) return;
    int h4 = (id & 31) * 4;
    const float* gr = &g_gates[(size_t)n * 512];
    float4 fg = *(const float4*)&gr[0   + h4];
    float4 ig = *(const float4*)&gr[128 + h4];
    float4 ug = *(const float4*)&gr[256 + h4];
    float4 og = *(const float4*)&gr[384 + h4];
    float4 cs = *(const float4*)&g_csum[(size_t)n * 128 + h4];
    float4 c, h;
    c.x = fmaf(ig.x, ug.x, fg.x * cs.x);  h.x = og.x * tanhf(c.x);
    c.y = fmaf(ig.y, ug.y, fg.y * cs.y);  h.y = og.y * tanhf(c.y);
    c.z = fmaf(ig.z, ug.z, fg.z * cs.z);  h.z = og.z * tanhf(c.z);
    c.w = fmaf(ig.w, ug.w, fg.w * cs.w);  h.w = og.w * tanhf(c.w);
    *(float4*)&out[(size_t)n * 256 + h4]       = h;
    *(float4*)&out[(size_t)n * 256 + 128 + h4] = c;
}

// ---------------------------------------------------------------------------
// Launch
// ---------------------------------------------------------------------------
extern "C" void kernel_launch(void* const* d_in, const int* in_sizes, int n_in,
                              void* d_out, int out_size)
{
    const float* h_src = (const float*)d_in[0];
    const float* c_src = (const float*)d_in[1];
    const float* embed = (const float*)d_in[2];
    const float* sfeat = (const float*)d_in[3];
    const float* dfeat = (const float*)d_in[4];
    const float* Wf  = (const float*)d_in[5];
    const float* bWf = (const float*)d_in[6];
    const float* bf  = (const float*)d_in[7];
    const float* Wi  = (const float*)d_in[8];
    const float* bWi = (const float*)d_in[9];
    const float* bi  = (const float*)d_in[10];
    const float* Wu  = (const float*)d_in[11];
    const float* bWu = (const float*)d_in[12];
    const float* bu  = (const float*)d_in[13];
    const float* Wo  = (const float*)d_in[14];
    const float* bWo = (const float*)d_in[15];
    const float* bo  = (const float*)d_in[16];
    const float* W_eoh = (const float*)d_in[17];
    const float* b_eoh = (const float*)d_in[18];
    const float* W_el  = (const float*)d_in[19];
    const float* b_el  = (const float*)d_in[20];
    const void*  etype = d_in[21];
    const void*  dsti  = d_in[22];

    const int E = in_sizes[0] / 128;
    const int N = out_size   / 256;

    cudaFuncSetAttribute(k_edgemm, cudaFuncAttributeMaxDynamicSharedMemorySize,
                         (int)sizeof(EdgeSm));

    // 1) index dtype probe
    k_detect<<<1, 1>>>((const unsigned int*)dsti);

    // 2) zero scatter targets (h_sum + c_sum)
    const int n4h = N * 64, n4c = N * 32;
    k_zero<<<(n4h + n4c + 255) / 256, 256>>>(n4h, n4c);

    // 3) pack biases / W_el pair image / bf16 gate-weight pair images
    k_pack<<<32, 256>>>(bWf, bf, bWi, bi, bWu, bu, bWo, bo, W_el);
    k_packB<<<256, 256>>>(Wf, Wi, Wu, Wo);

    // 4) edge-message GEMM (tensor) + scatter h_sum / embed / c_sum
    k_edgemm<<<(E + 127) / 128, 256, sizeof(EdgeSm)>>>(
        h_src, embed, c_src, sfeat, dfeat, W_eoh, b_eoh, b_el, etype, dsti, E);

    // 5) gate GEMM (mma.sync bf16 3-term, double-buffered) + activations
    dim3 gg(4, (N + 127) / 128);
    k_mgemm<<<gg, 256>>>(N);

    // 6) finalize:  c = i*u + f*c_sum ; h = o*tanh(c)
    k_final<<<(N * 32 + 255) / 256, 256>>>((float*)d_out, N);
}